// round 12
// baseline (speedup 1.0000x reference)
#include <cuda_runtime.h>

#define BIGF 1e10f

// ---------------- scratch (no allocations allowed) ----------------
__device__ int    g_cidx[8 * 1024];
__device__ int    g_gidx[8 * 1024 * 32];
__device__ float  g_pfeat[8 * 4096 * 128];
__device__ float4 g_xyzw[8 * 4096];
__device__ volatile int g_prog[8];       // fps centroids published per batch
__device__ volatile int g_bq_prog[8];    // ballq prefix published per batch
__device__ volatile int g_pm_cnt;        // pmlp blocks finished

// ---------------- f32x2 helpers ----------------
__device__ __forceinline__ void ffma2(unsigned long long& acc,
                                      unsigned long long a, unsigned long long b)
{
    asm("fma.rn.f32x2 %0, %1, %2, %0;" : "+l"(acc) : "l"(a), "l"(b));
}
__device__ __forceinline__ unsigned long long mul2(unsigned long long a,
                                                   unsigned long long b)
{
    unsigned long long r;
    asm("mul.rn.f32x2 %0, %1, %2;" : "=l"(r) : "l"(a), "l"(b));
    return r;
}
__device__ __forceinline__ unsigned long long add2(unsigned long long a,
                                                   unsigned long long b)
{
    unsigned long long r;
    asm("add.rn.f32x2 %0, %1, %2;" : "=l"(r) : "l"(a), "l"(b));
    return r;
}
__device__ __forceinline__ unsigned long long pack2(float lo, float hi)
{
    unsigned long long r;
    asm("mov.b64 %0, {%1, %2};" : "=l"(r) : "f"(lo), "f"(hi));
    return r;
}
__device__ __forceinline__ float2 unpack2(unsigned long long v)
{
    float2 r;
    asm("mov.b64 {%0, %1}, %2;" : "=f"(r.x), "=f"(r.y) : "l"(v));
    return r;
}

// =================================================================
// reset (graph replays reuse device globals)
// =================================================================
__global__ void reset_kernel()
{
    if (threadIdx.x < 8)  { g_prog[threadIdx.x] = 0; g_bq_prog[threadIdx.x] = 0; }
    if (threadIdx.x == 8) g_pm_cnt = 0;
}

// =================================================================
// 32-row MLP layer (128-thread group): lane = row, warp gwp owns
// DCP channels from d0. f32x2 chain identical to proven mlp_pass.
// =================================================================
template <int Cin, int DCP>
__device__ __forceinline__ void mlp32(
    const float* __restrict__ W, const float* __restrict__ bb,
    const float* __restrict__ gg, const float* __restrict__ be,
    int d0, const float* __restrict__ xs, float* __restrict__ ys,
    int ystr, int lane)
{
    unsigned long long acc2[DCP];
#pragma unroll
    for (int j = 0; j < DCP; ++j) acc2[j] = 0ull;
    const float* xr = xs + lane * 68;
    for (int c = 0; c < Cin; c += 4) {
        float4 x4 = *reinterpret_cast<const float4*>(xr + c);
        unsigned long long xa = pack2(x4.x, x4.y), xb = pack2(x4.z, x4.w);
#pragma unroll
        for (int j = 0; j < DCP; ++j) {
            ulonglong2 w2 = *reinterpret_cast<const ulonglong2*>(
                W + (size_t)(d0 + j) * Cin + c);
            ffma2(acc2[j], xa, w2.x);
            ffma2(acc2[j], xb, w2.y);
        }
    }
#pragma unroll
    for (int j = 0; j < DCP; ++j) {
        int d = d0 + j;
        float s = gg[d] / sqrtf(1.0f + 1e-5f);
        float2 va = unpack2(acc2[j]);
        float v = ((va.x + va.y) + bb[d]) * s + be[d];
        ys[lane * ystr + d] = fmaxf(v, 0.0f);
    }
}

// =================================================================
// MEGA kernel: 768 threads, 200448B dyn smem, 1 block/SM.
//   [0,8)        fps
//   [8,179)      pmlp (171 blocks x 192 rows, 6 groups of 128 thr)
//   [179,2227)   ballq (2048 blocks)
//   [2227,3595)  gatt (1368 blocks)
// =================================================================
__global__ __launch_bounds__(768, 1) void mega_kernel(
    const float* __restrict__ pts,
    const float* __restrict__ W0, const float* __restrict__ b0,
    const float* __restrict__ g0, const float* __restrict__ be0,
    const float* __restrict__ W1, const float* __restrict__ b1,
    const float* __restrict__ g1, const float* __restrict__ be1,
    const float* __restrict__ W2, const float* __restrict__ b2,
    const float* __restrict__ g2, const float* __restrict__ be2,
    const float* __restrict__ A, float* __restrict__ out)
{
    extern __shared__ float dynsm[];
    const int t = threadIdx.x, lane = t & 31, wp = t >> 5;

    if (blockIdx.x < 8) {
        // ======================= FPS =======================
        float4* s_xyz = reinterpret_cast<float4*>(dynsm);
        __shared__ unsigned s_wv[2][16];
        __shared__ int      s_wi[2][16];
        const int b = blockIdx.x;

        for (int j = t; j < 4096; j += 768) {
            const float* q = pts + ((size_t)b * 4096 + j) * 67;
            float x = q[0], y = q[1], z = q[2];
            float w = __fadd_rn(__fadd_rn(__fmul_rn(x, x), __fmul_rn(y, y)),
                                __fmul_rn(z, z));
            float4 v = make_float4(x, y, z, w);
            s_xyz[j] = v;
            g_xyzw[b * 4096 + j] = v;
        }
        __syncthreads();

        unsigned long long px2[4], py2[4], pz2[4];
        float ds[8];
        float cx = s_xyz[0].x, cy = s_xyz[0].y, cz = s_xyz[0].z;
        if (t < 512) {
#pragma unroll
            for (int k = 0; k < 4; ++k) {
                float4 qa = s_xyz[t + (2 * k) * 512];
                float4 qb = s_xyz[t + (2 * k + 1) * 512];
                px2[k] = pack2(qa.x, qb.x);
                py2[k] = pack2(qa.y, qb.y);
                pz2[k] = pack2(qa.z, qb.z);
                ds[2 * k] = BIGF; ds[2 * k + 1] = BIGF;
            }
            if (t == 0) g_cidx[b * 1024] = 0;
        }

        for (int step = 0; step < 1024; ++step) {
            const int par = step & 1;
            if (t < 512) {
                const unsigned long long ncx = pack2(-cx, -cx);
                const unsigned long long ncy = pack2(-cy, -cy);
                const unsigned long long ncz = pack2(-cz, -cz);
                float bv = -1.0f; int bi = 0x7fffffff;
#pragma unroll
                for (int k = 0; k < 4; ++k) {
                    unsigned long long dx = add2(px2[k], ncx);
                    unsigned long long dy = add2(py2[k], ncy);
                    unsigned long long dz = add2(pz2[k], ncz);
                    unsigned long long xx = mul2(dx, dx);
                    unsigned long long yy = mul2(dy, dy);
                    unsigned long long zz = mul2(dz, dz);
                    unsigned long long dd = add2(add2(xx, yy), zz);
                    float2 d2 = unpack2(dd);
                    float n0 = fminf(ds[2 * k], d2.x);     ds[2 * k] = n0;
                    float n1 = fminf(ds[2 * k + 1], d2.y); ds[2 * k + 1] = n1;
                    if (n0 > bv) { bv = n0; bi = t + (2 * k) * 512; }
                    if (n1 > bv) { bv = n1; bi = t + (2 * k + 1) * 512; }
                }
                unsigned uv = __float_as_uint(bv);
                unsigned m  = __reduce_max_sync(0xffffffffu, uv);
                int cand    = (uv == m) ? bi : 0x7fffffff;
                int mi      = (int)__reduce_min_sync(0xffffffffu, (unsigned)cand);
                if (lane == 0) { s_wv[par][wp] = m; s_wi[par][wp] = mi; }
            }
            __syncthreads();
            if (t < 512) {
                unsigned v2 = (lane < 16) ? s_wv[par][lane] : 0u;
                int      i2 = (lane < 16) ? s_wi[par][lane] : 0x7fffffff;
                unsigned m2 = __reduce_max_sync(0xffffffffu, v2);
                int     c2  = (v2 == m2 && lane < 16) ? i2 : 0x7fffffff;
                int f       = (int)__reduce_min_sync(0xffffffffu, (unsigned)c2);
                float4 c4 = s_xyz[f];
                cx = c4.x; cy = c4.y; cz = c4.z;
                if (t == 0) {
                    if (step + 1 < 1024) g_cidx[b * 1024 + step + 1] = f;
                    if ((step & 7) == 7) { __threadfence(); g_prog[b] = step + 2; }
                }
            }
        }
        if (t == 0) { __threadfence(); g_prog[b] = 1024; }

    } else if (blockIdx.x < 179) {
        // ======================= pmlp =======================
        const int pm = blockIdx.x - 8;
        const int grp = t / 128, gt = t % 128, glane = gt & 31, gwp = gt >> 5;
        int r0 = pm * 192 + grp * 32;
        if (r0 > 32768 - 32) r0 = 32768 - 32;       // clamp (duplicate, benign)
        float* x0g  = dynsm + grp * 6304;           // 32*68
        float* bufg = x0g + 2176;                   // x1 (stride 68) / fb (stride 129)

        for (int e = gt; e < 2048; e += 128) {
            int n = e >> 6, c = e & 63;
            x0g[n * 68 + c] = pts[(size_t)(r0 + n) * 67 + 3 + c];
        }
        __syncthreads();
        mlp32<64, 16>(W0, b0, g0, be0, gwp * 16, x0g, bufg, 68, glane);
        __syncthreads();
        mlp32<64, 16>(W1, b1, g1, be1, gwp * 16, bufg, x0g, 68, glane);
        __syncthreads();
        mlp32<64, 16>(W2, b2, g2, be2, gwp * 32,      x0g, bufg, 129, glane);
        mlp32<64, 16>(W2, b2, g2, be2, gwp * 32 + 16, x0g, bufg, 129, glane);
        __syncthreads();
        for (int e = gt; e < 4096; e += 128) {
            int n = e >> 7, c = e & 127;
            g_pfeat[(size_t)(r0 + n) * 128 + c] = bufg[n * 129 + c];
        }
        __syncthreads();
        if (t == 0) { __threadfence(); atomicAdd((int*)&g_pm_cnt, 1); }

    } else if (blockIdx.x < 2227) {
        // ======================= ballq =======================
        const int blk = blockIdx.x - 179, b = blk >> 8, p0 = (blk & 255) * 4;
        const int w = wp;
        float* cd0 = dynsm;                               // 4*1088 floats
        int*   ci0 = reinterpret_cast<int*>(dynsm + 4 * 1088);
        __shared__ int    cnt[4];
        __shared__ float4 cc[4];

        if (t == 0) {
            while (g_prog[b] < p0 + 4) __nanosleep(128);
            __threadfence();
        }
        __syncthreads();

        if (t < 4) {
            cnt[t] = 0;
            cc[t] = g_xyzw[b * 4096 + g_cidx[b * 1024 + p0 + t]];
        }
        __syncthreads();
        const float4 c0 = cc[0], c1 = cc[1], c2 = cc[2], c3 = cc[3];
        const float4* P4 = g_xyzw + (size_t)b * 4096;

        for (int j = t; j < 4096; j += 768) {
            float4 q = P4[j];
            float e0 = __fadd_rn(__fadd_rn(__fmul_rn(c0.x, q.x), __fmul_rn(c0.y, q.y)), __fmul_rn(c0.z, q.z));
            float e1 = __fadd_rn(__fadd_rn(__fmul_rn(c1.x, q.x), __fmul_rn(c1.y, q.y)), __fmul_rn(c1.z, q.z));
            float e2 = __fadd_rn(__fadd_rn(__fmul_rn(c2.x, q.x), __fmul_rn(c2.y, q.y)), __fmul_rn(c2.z, q.z));
            float e3 = __fadd_rn(__fadd_rn(__fmul_rn(c3.x, q.x), __fmul_rn(c3.y, q.y)), __fmul_rn(c3.z, q.z));
            float d0 = __fadd_rn(__fadd_rn(__fmul_rn(-2.0f, e0), c0.w), q.w);
            float d1 = __fadd_rn(__fadd_rn(__fmul_rn(-2.0f, e1), c1.w), q.w);
            float d2 = __fadd_rn(__fadd_rn(__fmul_rn(-2.0f, e2), c2.w), q.w);
            float d3 = __fadd_rn(__fadd_rn(__fmul_rn(-2.0f, e3), c3.w), q.w);
            if (d0 <= 0.04f) { int pos = atomicAdd(&cnt[0], 1); cd0[0 * 1088 + pos] = d0; ci0[0 * 1088 + pos] = j; }
            if (d1 <= 0.04f) { int pos = atomicAdd(&cnt[1], 1); cd0[1 * 1088 + pos] = d1; ci0[1 * 1088 + pos] = j; }
            if (d2 <= 0.04f) { int pos = atomicAdd(&cnt[2], 1); cd0[2 * 1088 + pos] = d2; ci0[2 * 1088 + pos] = j; }
            if (d3 <= 0.04f) { int pos = atomicAdd(&cnt[3], 1); cd0[3 * 1088 + pos] = d3; ci0[3 * 1088 + pos] = j; }
        }
        __syncthreads();

        if (w < 4) {
            const int n = cnt[w];
            float* wd = cd0 + w * 1088;
            int*   wi = ci0 + w * 1088;
            int first = 0;
            for (int k = 0; k < 32; ++k) {
                int outv;
                if (k < n) {
                    float bv = 1e30f; int bi = 0x7fffffff; int bp = 0;
                    for (int pos = lane; pos < n; pos += 32) {
                        float v = wd[pos];
                        int  idx = wi[pos];
                        if (v < bv || (v == bv && idx < bi)) { bv = v; bi = idx; bp = pos; }
                    }
#pragma unroll
                    for (int o = 16; o; o >>= 1) {
                        float ov = __shfl_down_sync(0xffffffffu, bv, o);
                        int   oi = __shfl_down_sync(0xffffffffu, bi, o);
                        int   op = __shfl_down_sync(0xffffffffu, bp, o);
                        if (ov < bv || (ov == bv && oi < bi)) { bv = ov; bi = oi; bp = op; }
                    }
                    bi = __shfl_sync(0xffffffffu, bi, 0);
                    bp = __shfl_sync(0xffffffffu, bp, 0);
                    if (lane == 0) wd[bp] = 1e30f;
                    __syncwarp();
                    if (k == 0) first = bi;
                    outv = bi;
                } else {
                    outv = first;
                }
                if (lane == 0) g_gidx[(size_t)(b * 1024 + p0 + w) * 32 + k] = outv;
            }
        }
        __syncthreads();
        if (t == 0) {                         // ordered prefix publish
            __threadfence();
            while (g_bq_prog[b] != p0) __nanosleep(64);
            g_bq_prog[b] = p0 + 4;
        }

    } else {
        // ======================= gatt (verbatim R10 + spin) =======================
        float* As  = dynsm;                 // 16768 floats (overlaid by att)
        float* att = dynsm;                 // 6 * 4128
        float* fb  = dynsm + 6 * 4128;      // 6 * 4224
        __shared__ float gx[6][96];
        __shared__ float cp[6][131];
        __shared__ int   gi[6][32];

        const int NBB = 171;
        const int gblk = blockIdx.x - 2227;
        const int b = gblk / NBB, base = (gblk % NBB) * 6;
        const int gp = wp % 3;
        const int s  = wp / 3;
        const int d0 = s * 16;
        const int gA = 2 * gp, gB = 2 * gp + 1;

        // stage A (independent of deps) while thread 0 will spin after
        for (int e = t; e < 4192; e += 768)
            reinterpret_cast<float4*>(As)[e] = reinterpret_cast<const float4*>(A)[e];

        if (t == 0) {
            int lim = base + 6; if (lim > 1024) lim = 1024;
            while (*(volatile int*)&g_pm_cnt < 171) __nanosleep(256);
            while (g_bq_prog[b] < lim) __nanosleep(256);
            __threadfence();
        }
        __syncthreads();

        if (t < 192) {
            int gg = t >> 5, n = t & 31;
            int p = base + gg; if (p > 1023) p = 1023;
            gi[gg][n] = g_gidx[(size_t)(b * 1024 + p) * 32 + n];
        }
        for (int e = t; e < 786; e += 768) {
            int gg = e / 131, c = e - gg * 131;
            int p = base + gg; if (p > 1023) p = 1023;
            int cid = g_cidx[b * 1024 + p];
            cp[gg][c] = (c < 3) ? pts[((size_t)b * 4096 + cid) * 67 + c]
                                : g_pfeat[((size_t)b * 4096 + cid) * 128 + (c - 3)];
        }
        __syncthreads();
        if (t < 576) {
            int gg = t / 96, r = (t % 96) / 3, c = t % 3;
            gx[gg][r * 3 + c] = pts[((size_t)b * 4096 + gi[gg][r]) * 67 + c];
        }
        for (int e = t; e < 6144; e += 768) {
            int gg = e >> 10, n = (e >> 5) & 31, c4 = e & 31;
            float4 v = *reinterpret_cast<const float4*>(
                g_pfeat + ((size_t)b * 4096 + gi[gg][n]) * 128 + c4 * 4);
            *reinterpret_cast<float4*>(fb + gg * 4224 + n * 132 + c4 * 4) = v;
        }
        __syncthreads();

        if (t < 18) {
            int gg = t / 3, c = t % 3;
            if (base + gg < 1024)
                out[(size_t)(b * 1024 + base + gg) * 131 + c] = cp[gg][c];
        }

        unsigned long long accA[8], accB[8];
#pragma unroll
        for (int j = 0; j < 8; ++j) { accA[j] = 0ull; accB[j] = 0ull; }
        const float* fbA = fb + gA * 4224 + lane * 132;
        const float* fbB = fb + gB * 4224 + lane * 132;
        const float* gxA = gx[gA] + lane * 3;
        const float* gxB = gx[gB] + lane * 3;
        const float* cpA = cp[gA];
        const float* cpB = cp[gB];

#pragma unroll
        for (int c = 0; c < 3; ++c) {
            float dvA = gxA[c] - cpA[c];
            float dvB = gxB[c] - cpB[c];
            unsigned long long pA = pack2(dvA, dvA);
            unsigned long long pB = pack2(dvB, dvB);
            const ulonglong2* Ar = reinterpret_cast<const ulonglong2*>(As + c * 128 + d0);
#pragma unroll
            for (int j2 = 0; j2 < 4; ++j2) {
                ulonglong2 w = Ar[j2];
                ffma2(accA[2 * j2], pA, w.x); ffma2(accA[2 * j2 + 1], pA, w.y);
                ffma2(accB[2 * j2], pB, w.x); ffma2(accB[2 * j2 + 1], pB, w.y);
            }
        }
        for (int cc = 0; cc < 128; ++cc) {
            float dvA = fbA[cc] - cpA[cc + 3];
            float dvB = fbB[cc] - cpB[cc + 3];
            unsigned long long pA = pack2(dvA, dvA);
            unsigned long long pB = pack2(dvB, dvB);
            const ulonglong2* Ar = reinterpret_cast<const ulonglong2*>(As + (cc + 3) * 128 + d0);
#pragma unroll
            for (int j2 = 0; j2 < 4; ++j2) {
                ulonglong2 w = Ar[j2];
                ffma2(accA[2 * j2], pA, w.x); ffma2(accA[2 * j2 + 1], pA, w.y);
                ffma2(accB[2 * j2], pB, w.x); ffma2(accB[2 * j2 + 1], pB, w.y);
            }
        }
        __syncthreads();   // done reading As before overlay

        float* agA = att + gA * 4128 + lane * 129 + d0;
        float* agB = att + gB * 4128 + lane * 129 + d0;
#pragma unroll
        for (int j = 0; j < 8; ++j) {
            float2 vA = unpack2(accA[j]);
            float2 vB = unpack2(accB[j]);
            agA[2 * j]     = (vA.x >= 0.f) ? vA.x : 0.2f * vA.x;
            agA[2 * j + 1] = (vA.y >= 0.f) ? vA.y : 0.2f * vA.y;
            agB[2 * j]     = (vB.x >= 0.f) ? vB.x : 0.2f * vB.x;
            agB[2 * j + 1] = (vB.y >= 0.f) ? vB.y : 0.2f * vB.y;
        }
        __syncthreads();

        {
            int gg = t >> 7, d = t & 127;
            const float* av = att + gg * 4128;
            const float* fv = fb + gg * 4224;
            float m = -3.4e38f;
#pragma unroll
            for (int n = 0; n < 32; ++n) m = fmaxf(m, av[n * 129 + d]);
            float ssum = 0.f, gacc = 0.f;
#pragma unroll
            for (int n = 0; n < 32; ++n) {
                float ev = expf(av[n * 129 + d] - m);
                ssum += ev;
                gacc += ev * fv[n * 132 + d];
            }
            if (base + gg < 1024)
                out[(size_t)(b * 1024 + base + gg) * 131 + 3 + d] = gacc / ssum;
        }
    }
}

// =================================================================
extern "C" void kernel_launch(void* const* d_in, const int* in_sizes, int n_in,
                              void* d_out, int out_size)
{
    const float* pts = (const float*)d_in[0];
    const float* W0 = (const float*)d_in[1];
    const float* b0 = (const float*)d_in[2];
    const float* g0 = (const float*)d_in[3];
    const float* be0 = (const float*)d_in[4];
    const float* W1 = (const float*)d_in[5];
    const float* b1 = (const float*)d_in[6];
    const float* g1 = (const float*)d_in[7];
    const float* be1 = (const float*)d_in[8];
    const float* W2 = (const float*)d_in[9];
    const float* b2 = (const float*)d_in[10];
    const float* g2 = (const float*)d_in[11];
    const float* be2 = (const float*)d_in[12];
    const float* A  = (const float*)d_in[13];
    float* out = (float*)d_out;

    static bool init = false;
    if (!init) {
        init = true;
        cudaFuncSetAttribute(mega_kernel, cudaFuncAttributeMaxDynamicSharedMemorySize, 200448);
    }

    reset_kernel<<<1, 32>>>();
    mega_kernel<<<3595, 768, 200448>>>(pts, W0, b0, g0, be0, W1, b1, g1, be1,
                                       W2, b2, g2, be2, A, out);
}

// round 13
// speedup vs baseline: 1.1510x; 1.1510x over previous
#include <cuda_runtime.h>

#define BIGF 1e10f

// ---------------- scratch (no allocations allowed) ----------------
__device__ int    g_cidx[8 * 1024];
__device__ int    g_gidx[8 * 1024 * 32];
__device__ float  g_pfeat[8 * 4096 * 128];
__device__ float4 g_xyzw[8 * 4096];
__device__ volatile int g_prog[8];       // fps centroids published per batch
__device__ volatile int g_bq_prog[8];    // ballq prefix published per batch
__device__ volatile int g_pm_cnt;        // pmlp blocks finished

// ---------------- f32x2 helpers ----------------
__device__ __forceinline__ void ffma2(unsigned long long& acc,
                                      unsigned long long a, unsigned long long b)
{
    asm("fma.rn.f32x2 %0, %1, %2, %0;" : "+l"(acc) : "l"(a), "l"(b));
}
__device__ __forceinline__ unsigned long long mul2(unsigned long long a,
                                                   unsigned long long b)
{
    unsigned long long r;
    asm("mul.rn.f32x2 %0, %1, %2;" : "=l"(r) : "l"(a), "l"(b));
    return r;
}
__device__ __forceinline__ unsigned long long add2(unsigned long long a,
                                                   unsigned long long b)
{
    unsigned long long r;
    asm("add.rn.f32x2 %0, %1, %2;" : "=l"(r) : "l"(a), "l"(b));
    return r;
}
__device__ __forceinline__ unsigned long long pack2(float lo, float hi)
{
    unsigned long long r;
    asm("mov.b64 %0, {%1, %2};" : "=l"(r) : "f"(lo), "f"(hi));
    return r;
}
__device__ __forceinline__ float2 unpack2(unsigned long long v)
{
    float2 r;
    asm("mov.b64 {%0, %1}, %2;" : "=f"(r.x), "=f"(r.y) : "l"(v));
    return r;
}

// =================================================================
// reset (graph replays reuse device globals)
// =================================================================
__global__ void reset_kernel()
{
    if (threadIdx.x < 8)  { g_prog[threadIdx.x] = 0; g_bq_prog[threadIdx.x] = 0; }
    if (threadIdx.x == 8) g_pm_cnt = 0;
}

// =================================================================
// 32-row MLP layer (128-thread group) — proven bit-identical (mega v1)
// =================================================================
template <int Cin, int DCP>
__device__ __forceinline__ void mlp32(
    const float* __restrict__ W, const float* __restrict__ bb,
    const float* __restrict__ gg, const float* __restrict__ be,
    int d0, const float* __restrict__ xs, float* __restrict__ ys,
    int ystr, int lane)
{
    unsigned long long acc2[DCP];
#pragma unroll
    for (int j = 0; j < DCP; ++j) acc2[j] = 0ull;
    const float* xr = xs + lane * 68;
    for (int c = 0; c < Cin; c += 4) {
        float4 x4 = *reinterpret_cast<const float4*>(xr + c);
        unsigned long long xa = pack2(x4.x, x4.y), xb = pack2(x4.z, x4.w);
#pragma unroll
        for (int j = 0; j < DCP; ++j) {
            ulonglong2 w2 = *reinterpret_cast<const ulonglong2*>(
                W + (size_t)(d0 + j) * Cin + c);
            ffma2(acc2[j], xa, w2.x);
            ffma2(acc2[j], xb, w2.y);
        }
    }
#pragma unroll
    for (int j = 0; j < DCP; ++j) {
        int d = d0 + j;
        float s = gg[d] / sqrtf(1.0f + 1e-5f);
        float2 va = unpack2(acc2[j]);
        float v = ((va.x + va.y) + bb[d]) * s + be[d];
        ys[lane * ystr + d] = fmaxf(v, 0.0f);
    }
}

// =================================================================
// MEGA v2: 512 threads, 134656B dyn smem.
//   [0,8)       fps (verbatim R11 role, all 512 threads active)
//   [8,264)     pmlp: 256 blocks x 128 rows (4 groups of 128 thr)
//   [264,4360)  interleaved: batch=j%8, q=j/8; q even -> ballq q/2,
//               q odd -> gatt q/2 (both 4 centroids / block)
// =================================================================
__global__ __launch_bounds__(512, 1) void mega2_kernel(
    const float* __restrict__ pts,
    const float* __restrict__ W0, const float* __restrict__ b0,
    const float* __restrict__ g0, const float* __restrict__ be0,
    const float* __restrict__ W1, const float* __restrict__ b1,
    const float* __restrict__ g1, const float* __restrict__ be1,
    const float* __restrict__ W2, const float* __restrict__ b2,
    const float* __restrict__ g2, const float* __restrict__ be2,
    const float* __restrict__ A, float* __restrict__ out)
{
    extern __shared__ float dynsm[];
    const int t = threadIdx.x, lane = t & 31, wp = t >> 5;

    if (blockIdx.x < 8) {
        // ======================= FPS (verbatim R11) =======================
        float4* s_xyz = reinterpret_cast<float4*>(dynsm);
        __shared__ unsigned s_wv[2][16];
        __shared__ int      s_wi[2][16];
        const int b = blockIdx.x;

        for (int j = t; j < 4096; j += 512) {
            const float* q = pts + ((size_t)b * 4096 + j) * 67;
            float x = q[0], y = q[1], z = q[2];
            float w = __fadd_rn(__fadd_rn(__fmul_rn(x, x), __fmul_rn(y, y)),
                                __fmul_rn(z, z));
            float4 v = make_float4(x, y, z, w);
            s_xyz[j] = v;
            g_xyzw[b * 4096 + j] = v;
        }
        __syncthreads();

        unsigned long long px2[4], py2[4], pz2[4];
        float ds[8];
#pragma unroll
        for (int k = 0; k < 4; ++k) {
            float4 qa = s_xyz[t + (2 * k) * 512];
            float4 qb = s_xyz[t + (2 * k + 1) * 512];
            px2[k] = pack2(qa.x, qb.x);
            py2[k] = pack2(qa.y, qb.y);
            pz2[k] = pack2(qa.z, qb.z);
            ds[2 * k] = BIGF; ds[2 * k + 1] = BIGF;
        }

        if (t == 0) g_cidx[b * 1024] = 0;
        float cx = s_xyz[0].x, cy = s_xyz[0].y, cz = s_xyz[0].z;

        for (int step = 0; step < 1024; ++step) {
            const unsigned long long ncx = pack2(-cx, -cx);
            const unsigned long long ncy = pack2(-cy, -cy);
            const unsigned long long ncz = pack2(-cz, -cz);
            float bv = -1.0f; int bi = 0x7fffffff;
#pragma unroll
            for (int k = 0; k < 4; ++k) {
                unsigned long long dx = add2(px2[k], ncx);
                unsigned long long dy = add2(py2[k], ncy);
                unsigned long long dz = add2(pz2[k], ncz);
                unsigned long long xx = mul2(dx, dx);
                unsigned long long yy = mul2(dy, dy);
                unsigned long long zz = mul2(dz, dz);
                unsigned long long dd = add2(add2(xx, yy), zz);
                float2 d2 = unpack2(dd);
                float n0 = fminf(ds[2 * k], d2.x);     ds[2 * k] = n0;
                float n1 = fminf(ds[2 * k + 1], d2.y); ds[2 * k + 1] = n1;
                if (n0 > bv) { bv = n0; bi = t + (2 * k) * 512; }
                if (n1 > bv) { bv = n1; bi = t + (2 * k + 1) * 512; }
            }
            unsigned uv = __float_as_uint(bv);
            unsigned m  = __reduce_max_sync(0xffffffffu, uv);
            int cand    = (uv == m) ? bi : 0x7fffffff;
            int mi      = (int)__reduce_min_sync(0xffffffffu, (unsigned)cand);
            const int par = step & 1;
            if (lane == 0) { s_wv[par][wp] = m; s_wi[par][wp] = mi; }
            __syncthreads();
            unsigned v2 = (lane < 16) ? s_wv[par][lane] : 0u;
            int      i2 = (lane < 16) ? s_wi[par][lane] : 0x7fffffff;
            unsigned m2 = __reduce_max_sync(0xffffffffu, v2);
            int     c2  = (v2 == m2 && lane < 16) ? i2 : 0x7fffffff;
            int f       = (int)__reduce_min_sync(0xffffffffu, (unsigned)c2);
            float4 c4 = s_xyz[f];
            cx = c4.x; cy = c4.y; cz = c4.z;
            if (t == 0) {
                if (step + 1 < 1024) g_cidx[b * 1024 + step + 1] = f;
                if ((step & 7) == 7) { __threadfence(); g_prog[b] = step + 2; }
            }
        }
        if (t == 0) { __threadfence(); g_prog[b] = 1024; }
        return;
    }

    if (blockIdx.x < 264) {
        // ======================= pmlp (4 x 32-row groups) =======================
        const int pm = blockIdx.x - 8;
        const int grp = t / 128, gt = t % 128, glane = gt & 31, gwp = gt >> 5;
        const int r0 = pm * 128 + grp * 32;           // 256*128 = 32768 exact
        float* x0g  = dynsm + grp * 6304;             // 32*68
        float* bufg = x0g + 2176;                     // x1(68) / fb(129)

        for (int e = gt; e < 2048; e += 128) {
            int n = e >> 6, c = e & 63;
            x0g[n * 68 + c] = pts[(size_t)(r0 + n) * 67 + 3 + c];
        }
        __syncthreads();
        mlp32<64, 16>(W0, b0, g0, be0, gwp * 16, x0g, bufg, 68, glane);
        __syncthreads();
        mlp32<64, 16>(W1, b1, g1, be1, gwp * 16, bufg, x0g, 68, glane);
        __syncthreads();
        mlp32<64, 16>(W2, b2, g2, be2, gwp * 32,      x0g, bufg, 129, glane);
        mlp32<64, 16>(W2, b2, g2, be2, gwp * 32 + 16, x0g, bufg, 129, glane);
        __syncthreads();
        for (int e = gt; e < 4096; e += 128) {
            int n = e >> 7, c = e & 127;
            g_pfeat[(size_t)(r0 + n) * 128 + c] = bufg[n * 129 + c];
        }
        __syncthreads();
        if (t == 0) { __threadfence(); atomicAdd((int*)&g_pm_cnt, 1); }
        return;
    }

    // ------- interleaved consumer stream -------
    const int j = blockIdx.x - 264;
    const int b = j & 7;
    const int q = j >> 3;

    if ((q & 1) == 0) {
        // ======================= ballq (verbatim R11 role) =======================
        const int p0 = (q >> 1) * 4;
        const int w = wp;
        float* cd0 = dynsm;                               // 4*1088 floats
        int*   ci0 = reinterpret_cast<int*>(dynsm + 4 * 1088);
        __shared__ int    cnt[4];
        __shared__ float4 cc[4];

        if (t == 0) {
            while (g_prog[b] < p0 + 4) __nanosleep(128);
            __threadfence();
        }
        __syncthreads();

        if (t < 4) {
            cnt[t] = 0;
            cc[t] = g_xyzw[b * 4096 + g_cidx[b * 1024 + p0 + t]];
        }
        __syncthreads();
        const float4 c0 = cc[0], c1 = cc[1], c2 = cc[2], c3 = cc[3];
        const float4* P4 = g_xyzw + (size_t)b * 4096;

        for (int jj = t; jj < 4096; jj += 512) {
            float4 qv = P4[jj];
            float e0 = __fadd_rn(__fadd_rn(__fmul_rn(c0.x, qv.x), __fmul_rn(c0.y, qv.y)), __fmul_rn(c0.z, qv.z));
            float e1 = __fadd_rn(__fadd_rn(__fmul_rn(c1.x, qv.x), __fmul_rn(c1.y, qv.y)), __fmul_rn(c1.z, qv.z));
            float e2 = __fadd_rn(__fadd_rn(__fmul_rn(c2.x, qv.x), __fmul_rn(c2.y, qv.y)), __fmul_rn(c2.z, qv.z));
            float e3 = __fadd_rn(__fadd_rn(__fmul_rn(c3.x, qv.x), __fmul_rn(c3.y, qv.y)), __fmul_rn(c3.z, qv.z));
            float d0 = __fadd_rn(__fadd_rn(__fmul_rn(-2.0f, e0), c0.w), qv.w);
            float d1 = __fadd_rn(__fadd_rn(__fmul_rn(-2.0f, e1), c1.w), qv.w);
            float d2 = __fadd_rn(__fadd_rn(__fmul_rn(-2.0f, e2), c2.w), qv.w);
            float d3 = __fadd_rn(__fadd_rn(__fmul_rn(-2.0f, e3), c3.w), qv.w);
            if (d0 <= 0.04f) { int pos = atomicAdd(&cnt[0], 1); cd0[0 * 1088 + pos] = d0; ci0[0 * 1088 + pos] = jj; }
            if (d1 <= 0.04f) { int pos = atomicAdd(&cnt[1], 1); cd0[1 * 1088 + pos] = d1; ci0[1 * 1088 + pos] = jj; }
            if (d2 <= 0.04f) { int pos = atomicAdd(&cnt[2], 1); cd0[2 * 1088 + pos] = d2; ci0[2 * 1088 + pos] = jj; }
            if (d3 <= 0.04f) { int pos = atomicAdd(&cnt[3], 1); cd0[3 * 1088 + pos] = d3; ci0[3 * 1088 + pos] = jj; }
        }
        __syncthreads();

        if (w < 4) {
            const int n = cnt[w];
            float* wd = cd0 + w * 1088;
            int*   wi = ci0 + w * 1088;
            int first = 0;
            for (int k = 0; k < 32; ++k) {
                int outv;
                if (k < n) {
                    float bv = 1e30f; int bi = 0x7fffffff; int bp = 0;
                    for (int pos = lane; pos < n; pos += 32) {
                        float v = wd[pos];
                        int  idx = wi[pos];
                        if (v < bv || (v == bv && idx < bi)) { bv = v; bi = idx; bp = pos; }
                    }
#pragma unroll
                    for (int o = 16; o; o >>= 1) {
                        float ov = __shfl_down_sync(0xffffffffu, bv, o);
                        int   oi = __shfl_down_sync(0xffffffffu, bi, o);
                        int   op = __shfl_down_sync(0xffffffffu, bp, o);
                        if (ov < bv || (ov == bv && oi < bi)) { bv = ov; bi = oi; bp = op; }
                    }
                    bi = __shfl_sync(0xffffffffu, bi, 0);
                    bp = __shfl_sync(0xffffffffu, bp, 0);
                    if (lane == 0) wd[bp] = 1e30f;
                    __syncwarp();
                    if (k == 0) first = bi;
                    outv = bi;
                } else {
                    outv = first;
                }
                if (lane == 0) g_gidx[(size_t)(b * 1024 + p0 + w) * 32 + k] = outv;
            }
        }
        __syncthreads();
        if (t == 0) {                         // ordered prefix publish
            __threadfence();
            while (g_bq_prog[b] != p0) __nanosleep(64);
            g_bq_prog[b] = p0 + 4;
        }
        return;
    }

    // ======================= gatt (verbatim R8 body + spin) =======================
    {
        float* As  = dynsm;                 // 16768 floats; reused as att
        float* fb  = dynsm + 16768;         // 4 * 4224 floats (stride 132)
        float* att = dynsm;                 // overlay (16512 <= 16768)
        __shared__ float gx[4][96];
        __shared__ float cp[4][131];
        __shared__ int   gi[4][32];

        const int base = (q >> 1) * 4;
        const int gp = wp & 1;              // centroid pair {2gp, 2gp+1}
        const int s  = wp >> 1;             // 16-channel slice
        const int d0 = s * 16;
        const int gA = 2 * gp, gB = 2 * gp + 1;

        // stage A (independent of deps)
        for (int e = t; e < 4192; e += 512)
            reinterpret_cast<float4*>(As)[e] = reinterpret_cast<const float4*>(A)[e];

        if (t == 0) {
            while (*(volatile int*)&g_pm_cnt < 256) __nanosleep(256);
            while (g_bq_prog[b] < base + 4) __nanosleep(256);
            __threadfence();
        }
        __syncthreads();

        if (t < 128) {
            int gg = t >> 5, n = t & 31;
            gi[gg][n] = g_gidx[(size_t)(b * 1024 + base + gg) * 32 + n];
        }
        for (int e = t; e < 524; e += 512) {
            int gg = e / 131, c = e - gg * 131;
            int cid = g_cidx[b * 1024 + base + gg];
            cp[gg][c] = (c < 3) ? pts[((size_t)b * 4096 + cid) * 67 + c]
                                : g_pfeat[((size_t)b * 4096 + cid) * 128 + (c - 3)];
        }
        __syncthreads();   // gi ready
        if (t < 384) {
            int gg = t / 96, r = (t % 96) / 3, c = t % 3;
            gx[gg][r * 3 + c] = pts[((size_t)b * 4096 + gi[gg][r]) * 67 + c];
        }
        for (int e = t; e < 4096; e += 512) {
            int gg = e >> 10, n = (e >> 5) & 31, c4 = e & 31;
            float4 v = *reinterpret_cast<const float4*>(
                g_pfeat + ((size_t)b * 4096 + gi[gg][n]) * 128 + c4 * 4);
            *reinterpret_cast<float4*>(fb + gg * 4224 + n * 132 + c4 * 4) = v;
        }
        __syncthreads();

        if (t < 12) {
            int gg = t / 3, c = t % 3;
            out[(size_t)(b * 1024 + base + gg) * 131 + c] = cp[gg][c];
        }

        unsigned long long accA[8], accB[8];
#pragma unroll
        for (int jj = 0; jj < 8; ++jj) { accA[jj] = 0ull; accB[jj] = 0ull; }
        const float* fbA = fb + gA * 4224 + lane * 132;
        const float* fbB = fb + gB * 4224 + lane * 132;
        const float* gxA = gx[gA] + lane * 3;
        const float* gxB = gx[gB] + lane * 3;
        const float* cpA = cp[gA];
        const float* cpB = cp[gB];

#pragma unroll
        for (int c = 0; c < 3; ++c) {
            float dvA = gxA[c] - cpA[c];
            float dvB = gxB[c] - cpB[c];
            unsigned long long pA = pack2(dvA, dvA);
            unsigned long long pB = pack2(dvB, dvB);
            const ulonglong2* Ar = reinterpret_cast<const ulonglong2*>(As + c * 128 + d0);
#pragma unroll
            for (int j2 = 0; j2 < 4; ++j2) {
                ulonglong2 w = Ar[j2];
                ffma2(accA[2 * j2], pA, w.x); ffma2(accA[2 * j2 + 1], pA, w.y);
                ffma2(accB[2 * j2], pB, w.x); ffma2(accB[2 * j2 + 1], pB, w.y);
            }
        }
        for (int cc = 0; cc < 128; ++cc) {
            float dvA = fbA[cc] - cpA[cc + 3];
            float dvB = fbB[cc] - cpB[cc + 3];
            unsigned long long pA = pack2(dvA, dvA);
            unsigned long long pB = pack2(dvB, dvB);
            const ulonglong2* Ar = reinterpret_cast<const ulonglong2*>(As + (cc + 3) * 128 + d0);
#pragma unroll
            for (int j2 = 0; j2 < 4; ++j2) {
                ulonglong2 w = Ar[j2];
                ffma2(accA[2 * j2], pA, w.x); ffma2(accA[2 * j2 + 1], pA, w.y);
                ffma2(accB[2 * j2], pB, w.x); ffma2(accB[2 * j2 + 1], pB, w.y);
            }
        }
        __syncthreads();   // everyone done READING As before overlaying with att

        float* agA = att + gA * 4128 + lane * 129 + d0;
        float* agB = att + gB * 4128 + lane * 129 + d0;
#pragma unroll
        for (int jj = 0; jj < 8; ++jj) {
            float2 vA = unpack2(accA[jj]);
            float2 vB = unpack2(accB[jj]);
            agA[2 * jj]     = (vA.x >= 0.f) ? vA.x : 0.2f * vA.x;
            agA[2 * jj + 1] = (vA.y >= 0.f) ? vA.y : 0.2f * vA.y;
            agB[2 * jj]     = (vB.x >= 0.f) ? vB.x : 0.2f * vB.x;
            agB[2 * jj + 1] = (vB.y >= 0.f) ? vB.y : 0.2f * vB.y;
        }
        __syncthreads();

        {
            int gg = t >> 7, d = t & 127;
            const float* av = att + gg * 4128;
            const float* fv = fb + gg * 4224;
            float m = -3.4e38f;
#pragma unroll
            for (int n = 0; n < 32; ++n) m = fmaxf(m, av[n * 129 + d]);
            float ssum = 0.f, gacc = 0.f;
#pragma unroll
            for (int n = 0; n < 32; ++n) {
                float ev = expf(av[n * 129 + d] - m);
                ssum += ev;
                gacc += ev * fv[n * 132 + d];
            }
            out[(size_t)(b * 1024 + base + gg) * 131 + 3 + d] = gacc / ssum;
        }
    }
}

// =================================================================
extern "C" void kernel_launch(void* const* d_in, const int* in_sizes, int n_in,
                              void* d_out, int out_size)
{
    const float* pts = (const float*)d_in[0];
    const float* W0 = (const float*)d_in[1];
    const float* b0 = (const float*)d_in[2];
    const float* g0 = (const float*)d_in[3];
    const float* be0 = (const float*)d_in[4];
    const float* W1 = (const float*)d_in[5];
    const float* b1 = (const float*)d_in[6];
    const float* g1 = (const float*)d_in[7];
    const float* be1 = (const float*)d_in[8];
    const float* W2 = (const float*)d_in[9];
    const float* b2 = (const float*)d_in[10];
    const float* g2 = (const float*)d_in[11];
    const float* be2 = (const float*)d_in[12];
    const float* A  = (const float*)d_in[13];
    float* out = (float*)d_out;

    static bool init = false;
    if (!init) {
        init = true;
        cudaFuncSetAttribute(mega2_kernel, cudaFuncAttributeMaxDynamicSharedMemorySize, 134656);
    }

    reset_kernel<<<1, 32>>>();
    mega2_kernel<<<8 + 256 + 4096, 512, 134656>>>(pts, W0, b0, g0, be0,
                                                  W1, b1, g1, be1,
                                                  W2, b2, g2, be2, A, out);
}

// round 14
// speedup vs baseline: 1.3662x; 1.1869x over previous
#include <cuda_runtime.h>

#define BIGF 1e10f

// ---------------- scratch (no allocations allowed) ----------------
__device__ int    g_cidx[8 * 1024];
__device__ int    g_gidx[8 * 1024 * 32];
__device__ float  g_pfeat[8 * 4096 * 128];   // per-point MLP output
__device__ float4 g_xyzw[8 * 4096];          // packed xyz + |x|^2 (written by fps)
__device__ volatile int g_prog[8];           // centroids published per batch

// ---------------- f32x2 helpers ----------------
__device__ __forceinline__ void ffma2(unsigned long long& acc,
                                      unsigned long long a, unsigned long long b)
{
    asm("fma.rn.f32x2 %0, %1, %2, %0;" : "+l"(acc) : "l"(a), "l"(b));
}
__device__ __forceinline__ unsigned long long mul2(unsigned long long a,
                                                   unsigned long long b)
{
    unsigned long long r;
    asm("mul.rn.f32x2 %0, %1, %2;" : "=l"(r) : "l"(a), "l"(b));
    return r;
}
__device__ __forceinline__ unsigned long long add2(unsigned long long a,
                                                   unsigned long long b)
{
    unsigned long long r;
    asm("add.rn.f32x2 %0, %1, %2;" : "=l"(r) : "l"(a), "l"(b));
    return r;
}
__device__ __forceinline__ unsigned long long pack2(float lo, float hi)
{
    unsigned long long r;
    asm("mov.b64 %0, {%1, %2};" : "=l"(r) : "f"(lo), "f"(hi));
    return r;
}
__device__ __forceinline__ float2 unpack2(unsigned long long v)
{
    float2 r;
    asm("mov.b64 {%0, %1}, %2;" : "=f"(r.x), "=f"(r.y) : "l"(v));
    return r;
}

// =================================================================
// Kernel 0: reset progress counters (graph replays reuse globals).
// =================================================================
__global__ void reset_kernel()
{
    if (threadIdx.x < 8) g_prog[threadIdx.x] = 0;
}

// =================================================================
// Kernel 1: fused FPS + ball query (verbatim R11 — proven 760).
// =================================================================
__global__ __launch_bounds__(512) void fpsbq_kernel(const float* __restrict__ pts)
{
    extern __shared__ float dynsm[];

    if (blockIdx.x < 8) {
        // ================= FPS role =================
        float4* s_xyz = reinterpret_cast<float4*>(dynsm);   // 4096 * 16B
        __shared__ unsigned s_wv[2][16];
        __shared__ int      s_wi[2][16];

        const int b = blockIdx.x;
        const int t = threadIdx.x;
        const int lane = t & 31, wp = t >> 5;

        for (int j = t; j < 4096; j += 512) {
            const float* q = pts + ((size_t)b * 4096 + j) * 67;
            float x = q[0], y = q[1], z = q[2];
            float w = __fadd_rn(__fadd_rn(__fmul_rn(x, x), __fmul_rn(y, y)),
                                __fmul_rn(z, z));
            float4 v = make_float4(x, y, z, w);
            s_xyz[j] = v;
            g_xyzw[b * 4096 + j] = v;
        }
        __syncthreads();

        unsigned long long px2[4], py2[4], pz2[4];
        float ds[8];
#pragma unroll
        for (int k = 0; k < 4; ++k) {
            float4 qa = s_xyz[t + (2 * k) * 512];
            float4 qb = s_xyz[t + (2 * k + 1) * 512];
            px2[k] = pack2(qa.x, qb.x);
            py2[k] = pack2(qa.y, qb.y);
            pz2[k] = pack2(qa.z, qb.z);
            ds[2 * k] = BIGF; ds[2 * k + 1] = BIGF;
        }

        if (t == 0) g_cidx[b * 1024] = 0;
        float cx = s_xyz[0].x, cy = s_xyz[0].y, cz = s_xyz[0].z;

        for (int step = 0; step < 1024; ++step) {
            const unsigned long long ncx = pack2(-cx, -cx);
            const unsigned long long ncy = pack2(-cy, -cy);
            const unsigned long long ncz = pack2(-cz, -cz);
            float bv = -1.0f; int bi = 0x7fffffff;
#pragma unroll
            for (int k = 0; k < 4; ++k) {
                unsigned long long dx = add2(px2[k], ncx);
                unsigned long long dy = add2(py2[k], ncy);
                unsigned long long dz = add2(pz2[k], ncz);
                unsigned long long xx = mul2(dx, dx);
                unsigned long long yy = mul2(dy, dy);
                unsigned long long zz = mul2(dz, dz);
                unsigned long long dd = add2(add2(xx, yy), zz);
                float2 d2 = unpack2(dd);
                float n0 = fminf(ds[2 * k], d2.x);     ds[2 * k] = n0;
                float n1 = fminf(ds[2 * k + 1], d2.y); ds[2 * k + 1] = n1;
                if (n0 > bv) { bv = n0; bi = t + (2 * k) * 512; }  // ascending j
                if (n1 > bv) { bv = n1; bi = t + (2 * k + 1) * 512; }
            }
            unsigned uv = __float_as_uint(bv);
            unsigned m  = __reduce_max_sync(0xffffffffu, uv);
            int cand    = (uv == m) ? bi : 0x7fffffff;
            int mi      = (int)__reduce_min_sync(0xffffffffu, (unsigned)cand);
            const int par = step & 1;
            if (lane == 0) { s_wv[par][wp] = m; s_wi[par][wp] = mi; }
            __syncthreads();
            unsigned v2 = (lane < 16) ? s_wv[par][lane] : 0u;
            int      i2 = (lane < 16) ? s_wi[par][lane] : 0x7fffffff;
            unsigned m2 = __reduce_max_sync(0xffffffffu, v2);
            int     c2  = (v2 == m2 && lane < 16) ? i2 : 0x7fffffff;
            int f       = (int)__reduce_min_sync(0xffffffffu, (unsigned)c2);
            float4 c4 = s_xyz[f];
            cx = c4.x; cy = c4.y; cz = c4.z;
            if (t == 0) {
                if (step + 1 < 1024) g_cidx[b * 1024 + step + 1] = f;
                if ((step & 7) == 7) { __threadfence(); g_prog[b] = step + 2; }
            }
        }
        if (t == 0) { __threadfence(); g_prog[b] = 1024; }
    } else {
        // ================= ballq role =================
        const int blk = blockIdx.x - 8, b = blk >> 8, p0 = (blk & 255) * 4;
        const int t = threadIdx.x, lane = t & 31, w = t >> 5;
        float* cd0 = dynsm;                                  // 4 * 1088 floats
        int*   ci0 = reinterpret_cast<int*>(dynsm + 4 * 1088);
        __shared__ int    cnt[4];
        __shared__ float4 cc[4];

        if (t == 0) {
            while (g_prog[b] < p0 + 4) __nanosleep(128);
            __threadfence();                                  // acquire
        }
        __syncthreads();

        if (t < 4) {
            cnt[t] = 0;
            cc[t] = g_xyzw[b * 4096 + g_cidx[b * 1024 + p0 + t]];
        }
        __syncthreads();
        const float4 c0 = cc[0], c1 = cc[1], c2 = cc[2], c3 = cc[3];
        const float4* P4 = g_xyzw + (size_t)b * 4096;

        for (int j = t; j < 4096; j += 512) {
            float4 q = P4[j];
            float e0 = __fadd_rn(__fadd_rn(__fmul_rn(c0.x, q.x), __fmul_rn(c0.y, q.y)), __fmul_rn(c0.z, q.z));
            float e1 = __fadd_rn(__fadd_rn(__fmul_rn(c1.x, q.x), __fmul_rn(c1.y, q.y)), __fmul_rn(c1.z, q.z));
            float e2 = __fadd_rn(__fadd_rn(__fmul_rn(c2.x, q.x), __fmul_rn(c2.y, q.y)), __fmul_rn(c2.z, q.z));
            float e3 = __fadd_rn(__fadd_rn(__fmul_rn(c3.x, q.x), __fmul_rn(c3.y, q.y)), __fmul_rn(c3.z, q.z));
            float d0 = __fadd_rn(__fadd_rn(__fmul_rn(-2.0f, e0), c0.w), q.w);
            float d1 = __fadd_rn(__fadd_rn(__fmul_rn(-2.0f, e1), c1.w), q.w);
            float d2 = __fadd_rn(__fadd_rn(__fmul_rn(-2.0f, e2), c2.w), q.w);
            float d3 = __fadd_rn(__fadd_rn(__fmul_rn(-2.0f, e3), c3.w), q.w);
            if (d0 <= 0.04f) { int pos = atomicAdd(&cnt[0], 1); cd0[0 * 1088 + pos] = d0; ci0[0 * 1088 + pos] = j; }
            if (d1 <= 0.04f) { int pos = atomicAdd(&cnt[1], 1); cd0[1 * 1088 + pos] = d1; ci0[1 * 1088 + pos] = j; }
            if (d2 <= 0.04f) { int pos = atomicAdd(&cnt[2], 1); cd0[2 * 1088 + pos] = d2; ci0[2 * 1088 + pos] = j; }
            if (d3 <= 0.04f) { int pos = atomicAdd(&cnt[3], 1); cd0[3 * 1088 + pos] = d3; ci0[3 * 1088 + pos] = j; }
        }
        __syncthreads();

        if (w < 4) {   // warp w extracts from its own list (proven logic)
            const int n = cnt[w];
            float* wd = cd0 + w * 1088;
            int*   wi = ci0 + w * 1088;
            int first = 0;
            for (int k = 0; k < 32; ++k) {
                int outv;
                if (k < n) {
                    float bv = 1e30f; int bi = 0x7fffffff; int bp = 0;
                    for (int pos = lane; pos < n; pos += 32) {
                        float v = wd[pos];
                        int  idx = wi[pos];
                        if (v < bv || (v == bv && idx < bi)) { bv = v; bi = idx; bp = pos; }
                    }
#pragma unroll
                    for (int o = 16; o; o >>= 1) {
                        float ov = __shfl_down_sync(0xffffffffu, bv, o);
                        int   oi = __shfl_down_sync(0xffffffffu, bi, o);
                        int   op = __shfl_down_sync(0xffffffffu, bp, o);
                        if (ov < bv || (ov == bv && oi < bi)) { bv = ov; bi = oi; bp = op; }
                    }
                    bi = __shfl_sync(0xffffffffu, bi, 0);
                    bp = __shfl_sync(0xffffffffu, bp, 0);
                    if (lane == 0) wd[bp] = 1e30f;
                    __syncwarp();
                    if (k == 0) first = bi;
                    outv = bi;
                } else {
                    outv = first;
                }
                if (lane == 0) g_gidx[(size_t)(b * 1024 + p0 + w) * 32 + k] = outv;
            }
        }
    }
}

// =================================================================
// MLP pass (proven R5 version).
// =================================================================
template <int Cin, int DCP>
__device__ __forceinline__ void mlp_pass(
    const float* __restrict__ W, const float* __restrict__ bb,
    const float* __restrict__ gg, const float* __restrict__ be,
    int d0,
    const float* __restrict__ xs, int xstride,
    float* __restrict__ ys, int ystride, int lane)
{
    unsigned long long accA[DCP], accB[DCP];
#pragma unroll
    for (int j = 0; j < DCP; ++j) { accA[j] = 0ull; accB[j] = 0ull; }
    const float* xrA = xs + lane * xstride;
    const float* xrB = xs + (lane + 32) * xstride;
    for (int c = 0; c < Cin; c += 4) {
        float4 a4 = *reinterpret_cast<const float4*>(xrA + c);
        float4 b4 = *reinterpret_cast<const float4*>(xrB + c);
        unsigned long long a01 = pack2(a4.x, a4.y), a23 = pack2(a4.z, a4.w);
        unsigned long long b01 = pack2(b4.x, b4.y), b23 = pack2(b4.z, b4.w);
#pragma unroll
        for (int j = 0; j < DCP; ++j) {
            ulonglong2 w2 = *reinterpret_cast<const ulonglong2*>(
                W + (size_t)(d0 + j) * Cin + c);
            ffma2(accA[j], a01, w2.x); ffma2(accA[j], a23, w2.y);
            ffma2(accB[j], b01, w2.x); ffma2(accB[j], b23, w2.y);
        }
    }
#pragma unroll
    for (int j = 0; j < DCP; ++j) {
        int d = d0 + j;
        float s = gg[d] / sqrtf(1.0f + 1e-5f);
        float2 va = unpack2(accA[j]);
        float2 vb = unpack2(accB[j]);
        float ya = ((va.x + va.y) + bb[d]) * s + be[d];
        float yb = ((vb.x + vb.y) + bb[d]) * s + be[d];
        ys[lane * ystride + d]        = fmaxf(ya, 0.0f);
        ys[(lane + 32) * ystride + d] = fmaxf(yb, 0.0f);
    }
}

// =================================================================
// Kernel 3: pointwise MLP on ALL 32768 points (proven R5 version).
// =================================================================
__global__ __launch_bounds__(128) void pmlp_kernel(
    const float* __restrict__ pts,
    const float* __restrict__ W0, const float* __restrict__ b0,
    const float* __restrict__ g0, const float* __restrict__ be0,
    const float* __restrict__ W1, const float* __restrict__ b1,
    const float* __restrict__ g1, const float* __restrict__ be1,
    const float* __restrict__ W2, const float* __restrict__ b2,
    const float* __restrict__ g2, const float* __restrict__ be2)
{
    extern __shared__ float sm[];
    float* x0 = sm;
    float* x1 = sm + 64 * 68;
    float* fb = sm + 2 * 64 * 68;
    const int t = threadIdx.x, lane = t & 31, wp = t >> 5;
    const int r0 = blockIdx.x * 64;

    for (int e = t; e < 4096; e += 128) {
        int n = e >> 6, c = e & 63;
        x0[n * 68 + c] = pts[(size_t)(r0 + n) * 67 + 3 + c];
    }
    __syncthreads();
    mlp_pass<64, 16>(W0, b0, g0, be0, wp * 16, x0, 68, x1, 68, lane);
    __syncthreads();
    mlp_pass<64, 16>(W1, b1, g1, be1, wp * 16, x1, 68, x0, 68, lane);
    __syncthreads();
    mlp_pass<64, 16>(W2, b2, g2, be2, wp * 32,      x0, 68, fb, 129, lane);
    mlp_pass<64, 16>(W2, b2, g2, be2, wp * 32 + 16, x0, 68, fb, 129, lane);
    __syncthreads();
    for (int e = t; e < 8192; e += 128) {
        int n = e >> 7, c = e & 127;
        g_pfeat[(size_t)(r0 + n) * 128 + c] = fb[n * 129 + c];
    }
}

// =================================================================
// Kernel 4: attention v5 — R10 structure (6 centroids, 768 thr,
// A in smem) with the cc loop float4-vectorized + unrolled x4.
// FFMA2 accumulation order unchanged -> bit-identical output.
// =================================================================
__global__ __launch_bounds__(768, 1) void gatt_kernel(
    const float* __restrict__ pts,
    const float* __restrict__ A, float* __restrict__ out)
{
    extern __shared__ float sm[];
    float* As  = sm;                 // 16768 floats (overlaid by att later)
    float* att = sm;                 // 6 * 4128 floats
    float* fb  = sm + 6 * 4128;      // 6 * 4224 floats
    __shared__ float gx[6][96];
    __shared__ float cp[6][131];
    __shared__ int   gi[6][32];

    const int NBB = 171;
    const int blk = blockIdx.x;
    const int b = blk / NBB, base = (blk % NBB) * 6;
    const int t = threadIdx.x, lane = t & 31, wp = t >> 5;
    const int gp = wp % 3;
    const int s  = wp / 3;
    const int d0 = s * 16;
    const int gA = 2 * gp, gB = 2 * gp + 1;

    for (int e = t; e < 4192; e += 768)
        reinterpret_cast<float4*>(As)[e] = reinterpret_cast<const float4*>(A)[e];

    if (t < 192) {
        int gg = t >> 5, n = t & 31;
        int p = base + gg; if (p > 1023) p = 1023;
        gi[gg][n] = g_gidx[(size_t)(b * 1024 + p) * 32 + n];
    }
    for (int e = t; e < 786; e += 768) {
        int gg = e / 131, c = e - gg * 131;
        int p = base + gg; if (p > 1023) p = 1023;
        int cid = g_cidx[b * 1024 + p];
        cp[gg][c] = (c < 3) ? pts[((size_t)b * 4096 + cid) * 67 + c]
                            : g_pfeat[((size_t)b * 4096 + cid) * 128 + (c - 3)];
    }
    __syncthreads();
    if (t < 576) {
        int gg = t / 96, r = (t % 96) / 3, c = t % 3;
        gx[gg][r * 3 + c] = pts[((size_t)b * 4096 + gi[gg][r]) * 67 + c];
    }
    for (int e = t; e < 6144; e += 768) {
        int gg = e >> 10, n = (e >> 5) & 31, c4 = e & 31;
        float4 v = *reinterpret_cast<const float4*>(
            g_pfeat + ((size_t)b * 4096 + gi[gg][n]) * 128 + c4 * 4);
        *reinterpret_cast<float4*>(fb + gg * 4224 + n * 132 + c4 * 4) = v;
    }
    __syncthreads();

    if (t < 18) {
        int gg = t / 3, c = t % 3;
        if (base + gg < 1024)
            out[(size_t)(b * 1024 + base + gg) * 131 + c] = cp[gg][c];
    }

    unsigned long long accA[8], accB[8];
#pragma unroll
    for (int j = 0; j < 8; ++j) { accA[j] = 0ull; accB[j] = 0ull; }
    const float* fbA = fb + gA * 4224 + lane * 132;
    const float* fbB = fb + gB * 4224 + lane * 132;
    const float* gxA = gx[gA] + lane * 3;
    const float* gxB = gx[gB] + lane * 3;
    const float* cpA = cp[gA];
    const float* cpB = cp[gB];

#pragma unroll
    for (int c = 0; c < 3; ++c) {
        float dvA = gxA[c] - cpA[c];
        float dvB = gxB[c] - cpB[c];
        unsigned long long pA = pack2(dvA, dvA);
        unsigned long long pB = pack2(dvB, dvB);
        const ulonglong2* Ar = reinterpret_cast<const ulonglong2*>(As + c * 128 + d0);
#pragma unroll
        for (int j2 = 0; j2 < 4; ++j2) {
            ulonglong2 w = Ar[j2];
            ffma2(accA[2 * j2], pA, w.x); ffma2(accA[2 * j2 + 1], pA, w.y);
            ffma2(accB[2 * j2], pB, w.x); ffma2(accB[2 * j2 + 1], pB, w.y);
        }
    }
    // vectorized + unrolled cc loop (4 channels per iteration);
    // accumulation order identical to the scalar loop.
#pragma unroll 4
    for (int cc = 0; cc < 128; cc += 4) {
        float4 a4 = *reinterpret_cast<const float4*>(fbA + cc);
        float4 b4 = *reinterpret_cast<const float4*>(fbB + cc);
        float fa[4] = { a4.x, a4.y, a4.z, a4.w };
        float fbv[4] = { b4.x, b4.y, b4.z, b4.w };
#pragma unroll
        for (int u = 0; u < 4; ++u) {
            float dvA = fa[u] - cpA[cc + u + 3];
            float dvB = fbv[u] - cpB[cc + u + 3];
            unsigned long long pA = pack2(dvA, dvA);
            unsigned long long pB = pack2(dvB, dvB);
            const ulonglong2* Ar = reinterpret_cast<const ulonglong2*>(As + (cc + u + 3) * 128 + d0);
#pragma unroll
            for (int j2 = 0; j2 < 4; ++j2) {
                ulonglong2 w = Ar[j2];
                ffma2(accA[2 * j2], pA, w.x); ffma2(accA[2 * j2 + 1], pA, w.y);
                ffma2(accB[2 * j2], pB, w.x); ffma2(accB[2 * j2 + 1], pB, w.y);
            }
        }
    }
    __syncthreads();   // everyone done READING As before overlaying with att

    float* agA = att + gA * 4128 + lane * 129 + d0;
    float* agB = att + gB * 4128 + lane * 129 + d0;
#pragma unroll
    for (int j = 0; j < 8; ++j) {
        float2 vA = unpack2(accA[j]);
        float2 vB = unpack2(accB[j]);
        agA[2 * j]     = (vA.x >= 0.f) ? vA.x : 0.2f * vA.x;
        agA[2 * j + 1] = (vA.y >= 0.f) ? vA.y : 0.2f * vA.y;
        agB[2 * j]     = (vB.x >= 0.f) ? vB.x : 0.2f * vB.x;
        agB[2 * j + 1] = (vB.y >= 0.f) ? vB.y : 0.2f * vB.y;
    }
    __syncthreads();

    {
        int gg = t >> 7, d = t & 127;
        const float* av = att + gg * 4128;
        const float* fv = fb + gg * 4224;
        float m = -3.4e38f;
#pragma unroll
        for (int n = 0; n < 32; ++n) m = fmaxf(m, av[n * 129 + d]);
        float ssum = 0.f, gacc = 0.f;
#pragma unroll
        for (int n = 0; n < 32; ++n) {
            float ev = expf(av[n * 129 + d] - m);
            ssum += ev;
            gacc += ev * fv[n * 132 + d];
        }
        if (base + gg < 1024)
            out[(size_t)(b * 1024 + base + gg) * 131 + 3 + d] = gacc / ssum;
    }
}

// =================================================================
extern "C" void kernel_launch(void* const* d_in, const int* in_sizes, int n_in,
                              void* d_out, int out_size)
{
    const float* pts = (const float*)d_in[0];
    const float* W0 = (const float*)d_in[1];
    const float* b0 = (const float*)d_in[2];
    const float* g0 = (const float*)d_in[3];
    const float* be0 = (const float*)d_in[4];
    const float* W1 = (const float*)d_in[5];
    const float* b1 = (const float*)d_in[6];
    const float* g1 = (const float*)d_in[7];
    const float* be1 = (const float*)d_in[8];
    const float* W2 = (const float*)d_in[9];
    const float* b2 = (const float*)d_in[10];
    const float* g2 = (const float*)d_in[11];
    const float* be2 = (const float*)d_in[12];
    const float* A  = (const float*)d_in[13];
    float* out = (float*)d_out;

    static cudaStream_t s1 = nullptr;
    static cudaEvent_t  e_fork = nullptr, e_join = nullptr;
    if (s1 == nullptr) {
        cudaStreamCreateWithFlags(&s1, cudaStreamNonBlocking);
        cudaEventCreateWithFlags(&e_fork, cudaEventDisableTiming);
        cudaEventCreateWithFlags(&e_join, cudaEventDisableTiming);
        cudaFuncSetAttribute(fpsbq_kernel, cudaFuncAttributeMaxDynamicSharedMemorySize, 65536);
        cudaFuncSetAttribute(pmlp_kernel,  cudaFuncAttributeMaxDynamicSharedMemorySize, 67840);
        cudaFuncSetAttribute(gatt_kernel,  cudaFuncAttributeMaxDynamicSharedMemorySize, 200448);
    }

    // fork: pmlp (depends only on pts) overlaps the fused fps+ballq kernel
    cudaEventRecord(e_fork, 0);
    cudaStreamWaitEvent(s1, e_fork, 0);
    pmlp_kernel<<<512, 128, 67840, s1>>>(pts, W0, b0, g0, be0, W1, b1, g1, be1,
                                         W2, b2, g2, be2);
    cudaEventRecord(e_join, s1);

    reset_kernel<<<1, 32>>>();
    fpsbq_kernel<<<8 + 2048, 512, 65536>>>(pts);

    cudaStreamWaitEvent(0, e_join, 0);
    gatt_kernel<<<8 * 171, 768, 200448>>>(pts, A, out);
}

// round 15
// speedup vs baseline: 1.4490x; 1.0607x over previous
#include <cuda_runtime.h>

#define BIGF 1e10f

// ---------------- scratch (no allocations allowed) ----------------
__device__ int    g_cidx[8 * 1024];
__device__ float  g_pfeat[8 * 4096 * 128];
__device__ float4 g_xyzw[8 * 4096];
__device__ volatile int g_prog[8];       // fps centroids published per batch
__device__ volatile int g_pm_done;       // pmlp chunks completed
__device__ int    g_pm_next;             // pmlp work-queue counter

// ---------------- f32x2 helpers ----------------
__device__ __forceinline__ void ffma2(unsigned long long& acc,
                                      unsigned long long a, unsigned long long b)
{
    asm("fma.rn.f32x2 %0, %1, %2, %0;" : "+l"(acc) : "l"(a), "l"(b));
}
__device__ __forceinline__ unsigned long long mul2(unsigned long long a,
                                                   unsigned long long b)
{
    unsigned long long r;
    asm("mul.rn.f32x2 %0, %1, %2;" : "=l"(r) : "l"(a), "l"(b));
    return r;
}
__device__ __forceinline__ unsigned long long add2(unsigned long long a,
                                                   unsigned long long b)
{
    unsigned long long r;
    asm("add.rn.f32x2 %0, %1, %2;" : "=l"(r) : "l"(a), "l"(b));
    return r;
}
__device__ __forceinline__ unsigned long long pack2(float lo, float hi)
{
    unsigned long long r;
    asm("mov.b64 %0, {%1, %2};" : "=l"(r) : "f"(lo), "f"(hi));
    return r;
}
__device__ __forceinline__ float2 unpack2(unsigned long long v)
{
    float2 r;
    asm("mov.b64 {%0, %1}, %2;" : "=f"(r.x), "=f"(r.y) : "l"(v));
    return r;
}

// =================================================================
// reset (graph replays reuse device globals)
// =================================================================
__global__ void reset_kernel()
{
    if (threadIdx.x < 8) g_prog[threadIdx.x] = 0;
    if (threadIdx.x == 8) { g_pm_done = 0; g_pm_next = 0; }
}

// =================================================================
// 32-row MLP layer (128-thread group) — proven bit-identical.
// =================================================================
template <int Cin, int DCP>
__device__ __forceinline__ void mlp32(
    const float* __restrict__ W, const float* __restrict__ bb,
    const float* __restrict__ gg, const float* __restrict__ be,
    int d0, const float* __restrict__ xs, float* __restrict__ ys,
    int ystr, int lane)
{
    unsigned long long acc2[DCP];
#pragma unroll
    for (int j = 0; j < DCP; ++j) acc2[j] = 0ull;
    const float* xr = xs + lane * 68;
    for (int c = 0; c < Cin; c += 4) {
        float4 x4 = *reinterpret_cast<const float4*>(xr + c);
        unsigned long long xa = pack2(x4.x, x4.y), xb = pack2(x4.z, x4.w);
#pragma unroll
        for (int j = 0; j < DCP; ++j) {
            ulonglong2 w2 = *reinterpret_cast<const ulonglong2*>(
                W + (size_t)(d0 + j) * Cin + c);
            ffma2(acc2[j], xa, w2.x);
            ffma2(acc2[j], xb, w2.y);
        }
    }
#pragma unroll
    for (int j = 0; j < DCP; ++j) {
        int d = d0 + j;
        float s = gg[d] / sqrtf(1.0f + 1e-5f);
        float2 va = unpack2(acc2[j]);
        float v = ((va.x + va.y) + bb[d]) * s + be[d];
        ys[lane * ystr + d] = fmaxf(v, 0.0f);
    }
}

// =================================================================
// MEGA v3: grid = 8 (fps) + 1368 (consumers), 768 thr, 200448B smem.
// Consumers: pmlp work-queue -> spin fps -> local ballq -> spin pmlp
//            -> gatt. No consumer-to-consumer dependencies.
// =================================================================
__global__ __launch_bounds__(768, 1) void mega3_kernel(
    const float* __restrict__ pts,
    const float* __restrict__ W0, const float* __restrict__ b0,
    const float* __restrict__ g0, const float* __restrict__ be0,
    const float* __restrict__ W1, const float* __restrict__ b1,
    const float* __restrict__ g1, const float* __restrict__ be1,
    const float* __restrict__ W2, const float* __restrict__ b2,
    const float* __restrict__ g2, const float* __restrict__ be2,
    const float* __restrict__ A, float* __restrict__ out)
{
    extern __shared__ float dynsm[];
    const int t = threadIdx.x, lane = t & 31, wp = t >> 5;

    if (blockIdx.x < 8) {
        // ======================= FPS (verbatim mega-v1 role) =======================
        float4* s_xyz = reinterpret_cast<float4*>(dynsm);
        __shared__ unsigned s_wv[2][16];
        __shared__ int      s_wi[2][16];
        const int b = blockIdx.x;

        for (int j = t; j < 4096; j += 768) {
            const float* q = pts + ((size_t)b * 4096 + j) * 67;
            float x = q[0], y = q[1], z = q[2];
            float w = __fadd_rn(__fadd_rn(__fmul_rn(x, x), __fmul_rn(y, y)),
                                __fmul_rn(z, z));
            float4 v = make_float4(x, y, z, w);
            s_xyz[j] = v;
            g_xyzw[b * 4096 + j] = v;
        }
        __syncthreads();

        unsigned long long px2[4], py2[4], pz2[4];
        float ds[8];
        float cx = s_xyz[0].x, cy = s_xyz[0].y, cz = s_xyz[0].z;
        if (t < 512) {
#pragma unroll
            for (int k = 0; k < 4; ++k) {
                float4 qa = s_xyz[t + (2 * k) * 512];
                float4 qb = s_xyz[t + (2 * k + 1) * 512];
                px2[k] = pack2(qa.x, qb.x);
                py2[k] = pack2(qa.y, qb.y);
                pz2[k] = pack2(qa.z, qb.z);
                ds[2 * k] = BIGF; ds[2 * k + 1] = BIGF;
            }
            if (t == 0) g_cidx[b * 1024] = 0;
        }

        for (int step = 0; step < 1024; ++step) {
            const int par = step & 1;
            if (t < 512) {
                const unsigned long long ncx = pack2(-cx, -cx);
                const unsigned long long ncy = pack2(-cy, -cy);
                const unsigned long long ncz = pack2(-cz, -cz);
                float bv = -1.0f; int bi = 0x7fffffff;
#pragma unroll
                for (int k = 0; k < 4; ++k) {
                    unsigned long long dx = add2(px2[k], ncx);
                    unsigned long long dy = add2(py2[k], ncy);
                    unsigned long long dz = add2(pz2[k], ncz);
                    unsigned long long xx = mul2(dx, dx);
                    unsigned long long yy = mul2(dy, dy);
                    unsigned long long zz = mul2(dz, dz);
                    unsigned long long dd = add2(add2(xx, yy), zz);
                    float2 d2 = unpack2(dd);
                    float n0 = fminf(ds[2 * k], d2.x);     ds[2 * k] = n0;
                    float n1 = fminf(ds[2 * k + 1], d2.y); ds[2 * k + 1] = n1;
                    if (n0 > bv) { bv = n0; bi = t + (2 * k) * 512; }
                    if (n1 > bv) { bv = n1; bi = t + (2 * k + 1) * 512; }
                }
                unsigned uv = __float_as_uint(bv);
                unsigned m  = __reduce_max_sync(0xffffffffu, uv);
                int cand    = (uv == m) ? bi : 0x7fffffff;
                int mi      = (int)__reduce_min_sync(0xffffffffu, (unsigned)cand);
                if (lane == 0) { s_wv[par][wp] = m; s_wi[par][wp] = mi; }
            }
            __syncthreads();
            if (t < 512) {
                unsigned v2 = (lane < 16) ? s_wv[par][lane] : 0u;
                int      i2 = (lane < 16) ? s_wi[par][lane] : 0x7fffffff;
                unsigned m2 = __reduce_max_sync(0xffffffffu, v2);
                int     c2  = (v2 == m2 && lane < 16) ? i2 : 0x7fffffff;
                int f       = (int)__reduce_min_sync(0xffffffffu, (unsigned)c2);
                float4 c4 = s_xyz[f];
                cx = c4.x; cy = c4.y; cz = c4.z;
                if (t == 0) {
                    if (step + 1 < 1024) g_cidx[b * 1024 + step + 1] = f;
                    if ((step & 7) == 7) { __threadfence(); g_prog[b] = step + 2; }
                }
            }
        }
        if (t == 0) { __threadfence(); g_prog[b] = 1024; }
        return;
    }

    // ======================= consumer block =======================
    const int j = blockIdx.x - 8;
    const int NBB = 171;
    const int b = j / NBB, base = (j % NBB) * 6;

    __shared__ int    s_chunk;
    __shared__ float  gx[6][96];
    __shared__ float  cp[6][131];
    __shared__ int    gi[6][32];
    __shared__ int    cnt[6];
    __shared__ float4 cc[6];

    // ---- phase 1: drain pmlp work-queue (171 chunks x 192 rows) ----
    {
        const int grp = t / 128, gt = t % 128, glane = gt & 31, gwp = gt >> 5;
        float* x0g  = dynsm + grp * 6304;     // 32*68
        float* bufg = x0g + 2176;             // x1(68) / fb(129)
        for (;;) {
            if (t == 0) s_chunk = atomicAdd(&g_pm_next, 1);
            __syncthreads();
            const int c = s_chunk;
            if (c >= 171) break;
            int r0 = c * 192 + grp * 32;
            if (r0 > 32768 - 32) r0 = 32768 - 32;    // duplicate rows, same values
            for (int e = gt; e < 2048; e += 128) {
                int n = e >> 6, cch = e & 63;
                x0g[n * 68 + cch] = pts[(size_t)(r0 + n) * 67 + 3 + cch];
            }
            __syncthreads();
            mlp32<64, 16>(W0, b0, g0, be0, gwp * 16, x0g, bufg, 68, glane);
            __syncthreads();
            mlp32<64, 16>(W1, b1, g1, be1, gwp * 16, bufg, x0g, 68, glane);
            __syncthreads();
            mlp32<64, 16>(W2, b2, g2, be2, gwp * 32,      x0g, bufg, 129, glane);
            mlp32<64, 16>(W2, b2, g2, be2, gwp * 32 + 16, x0g, bufg, 129, glane);
            __syncthreads();
            for (int e = gt; e < 4096; e += 128) {
                int n = e >> 7, cch = e & 127;
                g_pfeat[(size_t)(r0 + n) * 128 + cch] = bufg[n * 129 + cch];
            }
            __syncthreads();
            if (t == 0) { __threadfence(); atomicAdd((int*)&g_pm_done, 1); }
            __syncthreads();
        }
    }

    // ---- phase 2: wait for fps to publish our centroids ----
    int lim = base + 6; if (lim > 1024) lim = 1024;
    if (t == 0) {
        while (g_prog[b] < lim) __nanosleep(256);
        __threadfence();
    }
    __syncthreads();

    // ---- phase 3: local ball query for 6 centroids ----
    {
        float* cd0 = dynsm;                                   // 6*1088 floats
        int*   ci0 = reinterpret_cast<int*>(dynsm + 6 * 1088);
        if (t < 6) {
            cnt[t] = 0;
            int p = base + t; if (p > 1023) p = 1023;
            cc[t] = g_xyzw[b * 4096 + g_cidx[b * 1024 + p]];
        }
        __syncthreads();
        const float4* P4 = g_xyzw + (size_t)b * 4096;
        for (int jj = t; jj < 4096; jj += 768) {
            float4 q = P4[jj];
#pragma unroll
            for (int g = 0; g < 6; ++g) {
                float4 cg = cc[g];
                float e = __fadd_rn(__fadd_rn(__fmul_rn(cg.x, q.x), __fmul_rn(cg.y, q.y)),
                                    __fmul_rn(cg.z, q.z));
                float d = __fadd_rn(__fadd_rn(__fmul_rn(-2.0f, e), cg.w), q.w);
                if (d <= 0.04f) {
                    int pos = atomicAdd(&cnt[g], 1);
                    cd0[g * 1088 + pos] = d;
                    ci0[g * 1088 + pos] = jj;
                }
            }
        }
        __syncthreads();

        if (wp < 6) {      // warp w extracts list w (verbatim proven logic)
            const int w = wp;
            const int n = cnt[w];
            float* wd = cd0 + w * 1088;
            int*   wi = ci0 + w * 1088;
            int first = 0;
            for (int k = 0; k < 32; ++k) {
                int outv;
                if (k < n) {
                    float bv = 1e30f; int bi = 0x7fffffff; int bp = 0;
                    for (int pos = lane; pos < n; pos += 32) {
                        float v = wd[pos];
                        int  idx = wi[pos];
                        if (v < bv || (v == bv && idx < bi)) { bv = v; bi = idx; bp = pos; }
                    }
#pragma unroll
                    for (int o = 16; o; o >>= 1) {
                        float ov = __shfl_down_sync(0xffffffffu, bv, o);
                        int   oi = __shfl_down_sync(0xffffffffu, bi, o);
                        int   op = __shfl_down_sync(0xffffffffu, bp, o);
                        if (ov < bv || (ov == bv && oi < bi)) { bv = ov; bi = oi; bp = op; }
                    }
                    bi = __shfl_sync(0xffffffffu, bi, 0);
                    bp = __shfl_sync(0xffffffffu, bp, 0);
                    if (lane == 0) wd[bp] = 1e30f;
                    __syncwarp();
                    if (k == 0) first = bi;
                    outv = bi;
                } else {
                    outv = first;
                }
                if (lane == 0) gi[w][k] = outv;
            }
        }
    }

    // ---- phase 4: wait for pmlp completion ----
    if (t == 0) {
        while (g_pm_done < 171) __nanosleep(256);
        __threadfence();
    }
    __syncthreads();

    // ---- phase 5: gatt (verbatim R14 v5) ----
    {
        float* As  = dynsm;                 // 16768 floats (overlaid by att)
        float* att = dynsm;                 // 6 * 4128
        float* fb  = dynsm + 6 * 4128;      // 6 * 4224
        const int gp = wp % 3;
        const int s  = wp / 3;
        const int d0 = s * 16;
        const int gA = 2 * gp, gB = 2 * gp + 1;

        for (int e = t; e < 4192; e += 768)
            reinterpret_cast<float4*>(As)[e] = reinterpret_cast<const float4*>(A)[e];

        for (int e = t; e < 786; e += 768) {
            int gg = e / 131, c = e - gg * 131;
            int p = base + gg; if (p > 1023) p = 1023;
            int cid = g_cidx[b * 1024 + p];
            cp[gg][c] = (c < 3) ? pts[((size_t)b * 4096 + cid) * 67 + c]
                                : g_pfeat[((size_t)b * 4096 + cid) * 128 + (c - 3)];
        }
        __syncthreads();
        if (t < 576) {
            int gg = t / 96, r = (t % 96) / 3, c = t % 3;
            gx[gg][r * 3 + c] = pts[((size_t)b * 4096 + gi[gg][r]) * 67 + c];
        }
        for (int e = t; e < 6144; e += 768) {
            int gg = e >> 10, n = (e >> 5) & 31, c4 = e & 31;
            float4 v = *reinterpret_cast<const float4*>(
                g_pfeat + ((size_t)b * 4096 + gi[gg][n]) * 128 + c4 * 4);
            *reinterpret_cast<float4*>(fb + gg * 4224 + n * 132 + c4 * 4) = v;
        }
        __syncthreads();

        if (t < 18) {
            int gg = t / 3, c = t % 3;
            if (base + gg < 1024)
                out[(size_t)(b * 1024 + base + gg) * 131 + c] = cp[gg][c];
        }

        unsigned long long accA[8], accB[8];
#pragma unroll
        for (int jj = 0; jj < 8; ++jj) { accA[jj] = 0ull; accB[jj] = 0ull; }
        const float* fbA = fb + gA * 4224 + lane * 132;
        const float* fbB = fb + gB * 4224 + lane * 132;
        const float* gxA = gx[gA] + lane * 3;
        const float* gxB = gx[gB] + lane * 3;
        const float* cpA = cp[gA];
        const float* cpB = cp[gB];

#pragma unroll
        for (int c = 0; c < 3; ++c) {
            float dvA = gxA[c] - cpA[c];
            float dvB = gxB[c] - cpB[c];
            unsigned long long pA = pack2(dvA, dvA);
            unsigned long long pB = pack2(dvB, dvB);
            const ulonglong2* Ar = reinterpret_cast<const ulonglong2*>(As + c * 128 + d0);
#pragma unroll
            for (int j2 = 0; j2 < 4; ++j2) {
                ulonglong2 w = Ar[j2];
                ffma2(accA[2 * j2], pA, w.x); ffma2(accA[2 * j2 + 1], pA, w.y);
                ffma2(accB[2 * j2], pB, w.x); ffma2(accB[2 * j2 + 1], pB, w.y);
            }
        }
#pragma unroll 4
        for (int cc2 = 0; cc2 < 128; cc2 += 4) {
            float4 a4 = *reinterpret_cast<const float4*>(fbA + cc2);
            float4 b4 = *reinterpret_cast<const float4*>(fbB + cc2);
            float fa[4] = { a4.x, a4.y, a4.z, a4.w };
            float fbv[4] = { b4.x, b4.y, b4.z, b4.w };
#pragma unroll
            for (int u = 0; u < 4; ++u) {
                float dvA = fa[u] - cpA[cc2 + u + 3];
                float dvB = fbv[u] - cpB[cc2 + u + 3];
                unsigned long long pA = pack2(dvA, dvA);
                unsigned long long pB = pack2(dvB, dvB);
                const ulonglong2* Ar = reinterpret_cast<const ulonglong2*>(As + (cc2 + u + 3) * 128 + d0);
#pragma unroll
                for (int j2 = 0; j2 < 4; ++j2) {
                    ulonglong2 w = Ar[j2];
                    ffma2(accA[2 * j2], pA, w.x); ffma2(accA[2 * j2 + 1], pA, w.y);
                    ffma2(accB[2 * j2], pB, w.x); ffma2(accB[2 * j2 + 1], pB, w.y);
                }
            }
        }
        __syncthreads();   // done reading As before overlay

        float* agA = att + gA * 4128 + lane * 129 + d0;
        float* agB = att + gB * 4128 + lane * 129 + d0;
#pragma unroll
        for (int jj = 0; jj < 8; ++jj) {
            float2 vA = unpack2(accA[jj]);
            float2 vB = unpack2(accB[jj]);
            agA[2 * jj]     = (vA.x >= 0.f) ? vA.x : 0.2f * vA.x;
            agA[2 * jj + 1] = (vA.y >= 0.f) ? vA.y : 0.2f * vA.y;
            agB[2 * jj]     = (vB.x >= 0.f) ? vB.x : 0.2f * vB.x;
            agB[2 * jj + 1] = (vB.y >= 0.f) ? vB.y : 0.2f * vB.y;
        }
        __syncthreads();

        {
            int gg = t >> 7, d = t & 127;
            const float* av = att + gg * 4128;
            const float* fv = fb + gg * 4224;
            float m = -3.4e38f;
#pragma unroll
            for (int n = 0; n < 32; ++n) m = fmaxf(m, av[n * 129 + d]);
            float ssum = 0.f, gacc = 0.f;
#pragma unroll
            for (int n = 0; n < 32; ++n) {
                float ev = expf(av[n * 129 + d] - m);
                ssum += ev;
                gacc += ev * fv[n * 132 + d];
            }
            if (base + gg < 1024)
                out[(size_t)(b * 1024 + base + gg) * 131 + 3 + d] = gacc / ssum;
        }
    }
}

// =================================================================
extern "C" void kernel_launch(void* const* d_in, const int* in_sizes, int n_in,
                              void* d_out, int out_size)
{
    const float* pts = (const float*)d_in[0];
    const float* W0 = (const float*)d_in[1];
    const float* b0 = (const float*)d_in[2];
    const float* g0 = (const float*)d_in[3];
    const float* be0 = (const float*)d_in[4];
    const float* W1 = (const float*)d_in[5];
    const float* b1 = (const float*)d_in[6];
    const float* g1 = (const float*)d_in[7];
    const float* be1 = (const float*)d_in[8];
    const float* W2 = (const float*)d_in[9];
    const float* b2 = (const float*)d_in[10];
    const float* g2 = (const float*)d_in[11];
    const float* be2 = (const float*)d_in[12];
    const float* A  = (const float*)d_in[13];
    float* out = (float*)d_out;

    static bool init = false;
    if (!init) {
        init = true;
        cudaFuncSetAttribute(mega3_kernel, cudaFuncAttributeMaxDynamicSharedMemorySize, 200448);
    }

    reset_kernel<<<1, 32>>>();
    mega3_kernel<<<8 + 1368, 768, 200448>>>(pts, W0, b0, g0, be0,
                                            W1, b1, g1, be1,
                                            W2, b2, g2, be2, A, out);
}

// round 16
// speedup vs baseline: 1.6776x; 1.1577x over previous
#include <cuda_runtime.h>

#define BIGF 1e10f

// ---------------- scratch (no allocations allowed) ----------------
__device__ int    g_cidx[8 * 1024];
__device__ float  g_pfeat[8 * 4096 * 128];
__device__ float4 g_xyzw[8 * 4096];
__device__ volatile int g_prog[8];       // fps centroids published per batch
__device__ volatile int g_pm_done;       // pmlp chunks completed
__device__ int    g_pm_next;             // pmlp work-queue counter
__device__ int    g_tile_next;           // gatt tile work-queue counter

// ---------------- f32x2 helpers ----------------
__device__ __forceinline__ void ffma2(unsigned long long& acc,
                                      unsigned long long a, unsigned long long b)
{
    asm("fma.rn.f32x2 %0, %1, %2, %0;" : "+l"(acc) : "l"(a), "l"(b));
}
__device__ __forceinline__ unsigned long long mul2(unsigned long long a,
                                                   unsigned long long b)
{
    unsigned long long r;
    asm("mul.rn.f32x2 %0, %1, %2;" : "=l"(r) : "l"(a), "l"(b));
    return r;
}
__device__ __forceinline__ unsigned long long add2(unsigned long long a,
                                                   unsigned long long b)
{
    unsigned long long r;
    asm("add.rn.f32x2 %0, %1, %2;" : "=l"(r) : "l"(a), "l"(b));
    return r;
}
__device__ __forceinline__ unsigned long long pack2(float lo, float hi)
{
    unsigned long long r;
    asm("mov.b64 %0, {%1, %2};" : "=l"(r) : "f"(lo), "f"(hi));
    return r;
}
__device__ __forceinline__ float2 unpack2(unsigned long long v)
{
    float2 r;
    asm("mov.b64 {%0, %1}, %2;" : "=f"(r.x), "=f"(r.y) : "l"(v));
    return r;
}

// =================================================================
// reset (graph replays reuse device globals)
// =================================================================
__global__ void reset_kernel()
{
    if (threadIdx.x < 8) g_prog[threadIdx.x] = 0;
    if (threadIdx.x == 8) { g_pm_done = 0; g_pm_next = 0; g_tile_next = 0; }
}

// =================================================================
// 32-row MLP layer (128-thread group) — proven bit-identical.
// =================================================================
template <int Cin, int DCP>
__device__ __forceinline__ void mlp32(
    const float* __restrict__ W, const float* __restrict__ bb,
    const float* __restrict__ gg, const float* __restrict__ be,
    int d0, const float* __restrict__ xs, float* __restrict__ ys,
    int ystr, int lane)
{
    unsigned long long acc2[DCP];
#pragma unroll
    for (int j = 0; j < DCP; ++j) acc2[j] = 0ull;
    const float* xr = xs + lane * 68;
    for (int c = 0; c < Cin; c += 4) {
        float4 x4 = *reinterpret_cast<const float4*>(xr + c);
        unsigned long long xa = pack2(x4.x, x4.y), xb = pack2(x4.z, x4.w);
#pragma unroll
        for (int j = 0; j < DCP; ++j) {
            ulonglong2 w2 = *reinterpret_cast<const ulonglong2*>(
                W + (size_t)(d0 + j) * Cin + c);
            ffma2(acc2[j], xa, w2.x);
            ffma2(acc2[j], xb, w2.y);
        }
    }
#pragma unroll
    for (int j = 0; j < DCP; ++j) {
        int d = d0 + j;
        float s = gg[d] / sqrtf(1.0f + 1e-5f);
        float2 va = unpack2(acc2[j]);
        float v = ((va.x + va.y) + bb[d]) * s + be[d];
        ys[lane * ystr + d] = fmaxf(v, 0.0f);
    }
}

// =================================================================
// MEGA v4: grid = 148 (8 fps + 140 persistent consumers), 768 thr,
// 200448B smem (1 block/SM, whole grid = wave 1).
// Consumers: pmlp queue -> wait pmlp -> tile queue loop
//            (spin fps -> local ballq -> gatt).
// =================================================================
__global__ __launch_bounds__(768, 1) void mega4_kernel(
    const float* __restrict__ pts,
    const float* __restrict__ W0, const float* __restrict__ b0,
    const float* __restrict__ g0, const float* __restrict__ be0,
    const float* __restrict__ W1, const float* __restrict__ b1,
    const float* __restrict__ g1, const float* __restrict__ be1,
    const float* __restrict__ W2, const float* __restrict__ b2,
    const float* __restrict__ g2, const float* __restrict__ be2,
    const float* __restrict__ A, float* __restrict__ out)
{
    extern __shared__ float dynsm[];
    const int t = threadIdx.x, lane = t & 31, wp = t >> 5;

    if (blockIdx.x < 8) {
        // ======================= FPS (verbatim mega-v3 role) =======================
        float4* s_xyz = reinterpret_cast<float4*>(dynsm);
        __shared__ unsigned s_wv[2][16];
        __shared__ int      s_wi[2][16];
        const int b = blockIdx.x;

        for (int j = t; j < 4096; j += 768) {
            const float* q = pts + ((size_t)b * 4096 + j) * 67;
            float x = q[0], y = q[1], z = q[2];
            float w = __fadd_rn(__fadd_rn(__fmul_rn(x, x), __fmul_rn(y, y)),
                                __fmul_rn(z, z));
            float4 v = make_float4(x, y, z, w);
            s_xyz[j] = v;
            g_xyzw[b * 4096 + j] = v;
        }
        __syncthreads();

        unsigned long long px2[4], py2[4], pz2[4];
        float ds[8];
        float cx = s_xyz[0].x, cy = s_xyz[0].y, cz = s_xyz[0].z;
        if (t < 512) {
#pragma unroll
            for (int k = 0; k < 4; ++k) {
                float4 qa = s_xyz[t + (2 * k) * 512];
                float4 qb = s_xyz[t + (2 * k + 1) * 512];
                px2[k] = pack2(qa.x, qb.x);
                py2[k] = pack2(qa.y, qb.y);
                pz2[k] = pack2(qa.z, qb.z);
                ds[2 * k] = BIGF; ds[2 * k + 1] = BIGF;
            }
            if (t == 0) g_cidx[b * 1024] = 0;
        }

        for (int step = 0; step < 1024; ++step) {
            const int par = step & 1;
            if (t < 512) {
                const unsigned long long ncx = pack2(-cx, -cx);
                const unsigned long long ncy = pack2(-cy, -cy);
                const unsigned long long ncz = pack2(-cz, -cz);
                float bv = -1.0f; int bi = 0x7fffffff;
#pragma unroll
                for (int k = 0; k < 4; ++k) {
                    unsigned long long dx = add2(px2[k], ncx);
                    unsigned long long dy = add2(py2[k], ncy);
                    unsigned long long dz = add2(pz2[k], ncz);
                    unsigned long long xx = mul2(dx, dx);
                    unsigned long long yy = mul2(dy, dy);
                    unsigned long long zz = mul2(dz, dz);
                    unsigned long long dd = add2(add2(xx, yy), zz);
                    float2 d2 = unpack2(dd);
                    float n0 = fminf(ds[2 * k], d2.x);     ds[2 * k] = n0;
                    float n1 = fminf(ds[2 * k + 1], d2.y); ds[2 * k + 1] = n1;
                    if (n0 > bv) { bv = n0; bi = t + (2 * k) * 512; }
                    if (n1 > bv) { bv = n1; bi = t + (2 * k + 1) * 512; }
                }
                unsigned uv = __float_as_uint(bv);
                unsigned m  = __reduce_max_sync(0xffffffffu, uv);
                int cand    = (uv == m) ? bi : 0x7fffffff;
                int mi      = (int)__reduce_min_sync(0xffffffffu, (unsigned)cand);
                if (lane == 0) { s_wv[par][wp] = m; s_wi[par][wp] = mi; }
            }
            __syncthreads();
            if (t < 512) {
                unsigned v2 = (lane < 16) ? s_wv[par][lane] : 0u;
                int      i2 = (lane < 16) ? s_wi[par][lane] : 0x7fffffff;
                unsigned m2 = __reduce_max_sync(0xffffffffu, v2);
                int     c2  = (v2 == m2 && lane < 16) ? i2 : 0x7fffffff;
                int f       = (int)__reduce_min_sync(0xffffffffu, (unsigned)c2);
                float4 c4 = s_xyz[f];
                cx = c4.x; cy = c4.y; cz = c4.z;
                if (t == 0) {
                    if (step + 1 < 1024) g_cidx[b * 1024 + step + 1] = f;
                    if ((step & 7) == 7) { __threadfence(); g_prog[b] = step + 2; }
                }
            }
        }
        if (t == 0) { __threadfence(); g_prog[b] = 1024; }
        return;
    }

    // ======================= persistent consumer =======================
    __shared__ int    s_chunk;
    __shared__ int    s_tile;
    __shared__ float  gx[6][96];
    __shared__ float  cp[6][131];
    __shared__ int    gi[6][32];
    __shared__ int    cnt[6];
    __shared__ float4 cc[6];

    // ---- phase 1: drain pmlp work-queue (171 chunks x 192 rows) ----
    {
        const int grp = t / 128, gt = t % 128, glane = gt & 31, gwp = gt >> 5;
        float* x0g  = dynsm + grp * 6304;     // 32*68
        float* bufg = x0g + 2176;             // x1(68) / fb(129)
        for (;;) {
            if (t == 0) s_chunk = atomicAdd(&g_pm_next, 1);
            __syncthreads();
            const int c = s_chunk;
            if (c >= 171) break;
            int r0 = c * 192 + grp * 32;
            if (r0 > 32768 - 32) r0 = 32768 - 32;    // duplicate rows, same values
            for (int e = gt; e < 2048; e += 128) {
                int n = e >> 6, cch = e & 63;
                x0g[n * 68 + cch] = pts[(size_t)(r0 + n) * 67 + 3 + cch];
            }
            __syncthreads();
            mlp32<64, 16>(W0, b0, g0, be0, gwp * 16, x0g, bufg, 68, glane);
            __syncthreads();
            mlp32<64, 16>(W1, b1, g1, be1, gwp * 16, bufg, x0g, 68, glane);
            __syncthreads();
            mlp32<64, 16>(W2, b2, g2, be2, gwp * 32,      x0g, bufg, 129, glane);
            mlp32<64, 16>(W2, b2, g2, be2, gwp * 32 + 16, x0g, bufg, 129, glane);
            __syncthreads();
            for (int e = gt; e < 4096; e += 128) {
                int n = e >> 7, cch = e & 127;
                g_pfeat[(size_t)(r0 + n) * 128 + cch] = bufg[n * 129 + cch];
            }
            __syncthreads();
            if (t == 0) { __threadfence(); atomicAdd((int*)&g_pm_done, 1); }
            __syncthreads();
        }
    }

    // ---- phase 2: wait for pmlp completion (once) ----
    if (t == 0) {
        while (g_pm_done < 171) __nanosleep(256);
        __threadfence();
    }
    __syncthreads();

    // ---- phase 3: persistent tile loop ----
    for (;;) {
        if (t == 0) s_tile = atomicAdd(&g_tile_next, 1);
        __syncthreads();
        const int idx = s_tile;
        if (idx >= 1368) return;
        const int b    = idx & 7;          // idx % 8
        const int base = (idx >> 3) * 6;   // ascending base == publish order

        int lim = base + 6; if (lim > 1024) lim = 1024;
        if (t == 0) {
            while (g_prog[b] < lim) __nanosleep(128);
            __threadfence();
        }
        __syncthreads();

        // ---- local ball query for 6 centroids ----
        {
            float* cd0 = dynsm;                                   // 6*1088 floats
            int*   ci0 = reinterpret_cast<int*>(dynsm + 6 * 1088);
            if (t < 6) {
                cnt[t] = 0;
                int p = base + t; if (p > 1023) p = 1023;
                cc[t] = g_xyzw[b * 4096 + g_cidx[b * 1024 + p]];
            }
            __syncthreads();
            const float4* P4 = g_xyzw + (size_t)b * 4096;
            for (int jj = t; jj < 4096; jj += 768) {
                float4 q = P4[jj];
#pragma unroll
                for (int g = 0; g < 6; ++g) {
                    float4 cg = cc[g];
                    float e = __fadd_rn(__fadd_rn(__fmul_rn(cg.x, q.x), __fmul_rn(cg.y, q.y)),
                                        __fmul_rn(cg.z, q.z));
                    float d = __fadd_rn(__fadd_rn(__fmul_rn(-2.0f, e), cg.w), q.w);
                    if (d <= 0.04f) {
                        int pos = atomicAdd(&cnt[g], 1);
                        cd0[g * 1088 + pos] = d;
                        ci0[g * 1088 + pos] = jj;
                    }
                }
            }
            __syncthreads();

            if (wp < 6) {      // warp w extracts list w (verbatim proven logic)
                const int w = wp;
                const int n = cnt[w];
                float* wd = cd0 + w * 1088;
                int*   wi = ci0 + w * 1088;
                int first = 0;
                for (int k = 0; k < 32; ++k) {
                    int outv;
                    if (k < n) {
                        float bv = 1e30f; int bi = 0x7fffffff; int bp = 0;
                        for (int pos = lane; pos < n; pos += 32) {
                            float v = wd[pos];
                            int  idxv = wi[pos];
                            if (v < bv || (v == bv && idxv < bi)) { bv = v; bi = idxv; bp = pos; }
                        }
#pragma unroll
                        for (int o = 16; o; o >>= 1) {
                            float ov = __shfl_down_sync(0xffffffffu, bv, o);
                            int   oi = __shfl_down_sync(0xffffffffu, bi, o);
                            int   op = __shfl_down_sync(0xffffffffu, bp, o);
                            if (ov < bv || (ov == bv && oi < bi)) { bv = ov; bi = oi; bp = op; }
                        }
                        bi = __shfl_sync(0xffffffffu, bi, 0);
                        bp = __shfl_sync(0xffffffffu, bp, 0);
                        if (lane == 0) wd[bp] = 1e30f;
                        __syncwarp();
                        if (k == 0) first = bi;
                        outv = bi;
                    } else {
                        outv = first;
                    }
                    if (lane == 0) gi[w][k] = outv;
                }
            }
        }

        // ---- gatt (verbatim R14 v5) ----
        {
            float* As  = dynsm;                 // 16768 floats (overlaid by att)
            float* att = dynsm;                 // 6 * 4128
            float* fb  = dynsm + 6 * 4128;      // 6 * 4224
            const int gp = wp % 3;
            const int s  = wp / 3;
            const int d0 = s * 16;
            const int gA = 2 * gp, gB = 2 * gp + 1;

            __syncthreads();   // ballq lists dead before As overlay
            for (int e = t; e < 4192; e += 768)
                reinterpret_cast<float4*>(As)[e] = reinterpret_cast<const float4*>(A)[e];

            for (int e = t; e < 786; e += 768) {
                int gg = e / 131, c = e - gg * 131;
                int p = base + gg; if (p > 1023) p = 1023;
                int cid = g_cidx[b * 1024 + p];
                cp[gg][c] = (c < 3) ? pts[((size_t)b * 4096 + cid) * 67 + c]
                                    : g_pfeat[((size_t)b * 4096 + cid) * 128 + (c - 3)];
            }
            __syncthreads();
            if (t < 576) {
                int gg = t / 96, r = (t % 96) / 3, c = t % 3;
                gx[gg][r * 3 + c] = pts[((size_t)b * 4096 + gi[gg][r]) * 67 + c];
            }
            for (int e = t; e < 6144; e += 768) {
                int gg = e >> 10, n = (e >> 5) & 31, c4 = e & 31;
                float4 v = *reinterpret_cast<const float4*>(
                    g_pfeat + ((size_t)b * 4096 + gi[gg][n]) * 128 + c4 * 4);
                *reinterpret_cast<float4*>(fb + gg * 4224 + n * 132 + c4 * 4) = v;
            }
            __syncthreads();

            if (t < 18) {
                int gg = t / 3, c = t % 3;
                if (base + gg < 1024)
                    out[(size_t)(b * 1024 + base + gg) * 131 + c] = cp[gg][c];
            }

            unsigned long long accA[8], accB[8];
#pragma unroll
            for (int jj = 0; jj < 8; ++jj) { accA[jj] = 0ull; accB[jj] = 0ull; }
            const float* fbA = fb + gA * 4224 + lane * 132;
            const float* fbB = fb + gB * 4224 + lane * 132;
            const float* gxA = gx[gA] + lane * 3;
            const float* gxB = gx[gB] + lane * 3;
            const float* cpA = cp[gA];
            const float* cpB = cp[gB];

#pragma unroll
            for (int c = 0; c < 3; ++c) {
                float dvA = gxA[c] - cpA[c];
                float dvB = gxB[c] - cpB[c];
                unsigned long long pA = pack2(dvA, dvA);
                unsigned long long pB = pack2(dvB, dvB);
                const ulonglong2* Ar = reinterpret_cast<const ulonglong2*>(As + c * 128 + d0);
#pragma unroll
                for (int j2 = 0; j2 < 4; ++j2) {
                    ulonglong2 w = Ar[j2];
                    ffma2(accA[2 * j2], pA, w.x); ffma2(accA[2 * j2 + 1], pA, w.y);
                    ffma2(accB[2 * j2], pB, w.x); ffma2(accB[2 * j2 + 1], pB, w.y);
                }
            }
#pragma unroll 4
            for (int cc2 = 0; cc2 < 128; cc2 += 4) {
                float4 a4 = *reinterpret_cast<const float4*>(fbA + cc2);
                float4 b4 = *reinterpret_cast<const float4*>(fbB + cc2);
                float fa[4] = { a4.x, a4.y, a4.z, a4.w };
                float fbv[4] = { b4.x, b4.y, b4.z, b4.w };
#pragma unroll
                for (int u = 0; u < 4; ++u) {
                    float dvA = fa[u] - cpA[cc2 + u + 3];
                    float dvB = fbv[u] - cpB[cc2 + u + 3];
                    unsigned long long pA = pack2(dvA, dvA);
                    unsigned long long pB = pack2(dvB, dvB);
                    const ulonglong2* Ar = reinterpret_cast<const ulonglong2*>(As + (cc2 + u + 3) * 128 + d0);
#pragma unroll
                    for (int j2 = 0; j2 < 4; ++j2) {
                        ulonglong2 w = Ar[j2];
                        ffma2(accA[2 * j2], pA, w.x); ffma2(accA[2 * j2 + 1], pA, w.y);
                        ffma2(accB[2 * j2], pB, w.x); ffma2(accB[2 * j2 + 1], pB, w.y);
                    }
                }
            }
            __syncthreads();   // done reading As before overlay

            float* agA = att + gA * 4128 + lane * 129 + d0;
            float* agB = att + gB * 4128 + lane * 129 + d0;
#pragma unroll
            for (int jj = 0; jj < 8; ++jj) {
                float2 vA = unpack2(accA[jj]);
                float2 vB = unpack2(accB[jj]);
                agA[2 * jj]     = (vA.x >= 0.f) ? vA.x : 0.2f * vA.x;
                agA[2 * jj + 1] = (vA.y >= 0.f) ? vA.y : 0.2f * vA.y;
                agB[2 * jj]     = (vB.x >= 0.f) ? vB.x : 0.2f * vB.x;
                agB[2 * jj + 1] = (vB.y >= 0.f) ? vB.y : 0.2f * vB.y;
            }
            __syncthreads();

            {
                int gg = t >> 7, d = t & 127;
                const float* av = att + gg * 4128;
                const float* fv = fb + gg * 4224;
                float m = -3.4e38f;
#pragma unroll
                for (int n = 0; n < 32; ++n) m = fmaxf(m, av[n * 129 + d]);
                float ssum = 0.f, gacc = 0.f;
#pragma unroll
                for (int n = 0; n < 32; ++n) {
                    float ev = expf(av[n * 129 + d] - m);
                    ssum += ev;
                    gacc += ev * fv[n * 132 + d];
                }
                if (base + gg < 1024)
                    out[(size_t)(b * 1024 + base + gg) * 131 + 3 + d] = gacc / ssum;
            }
            __syncthreads();   // smem dead before next tile
        }
    }
}

// =================================================================
extern "C" void kernel_launch(void* const* d_in, const int* in_sizes, int n_in,
                              void* d_out, int out_size)
{
    const float* pts = (const float*)d_in[0];
    const float* W0 = (const float*)d_in[1];
    const float* b0 = (const float*)d_in[2];
    const float* g0 = (const float*)d_in[3];
    const float* be0 = (const float*)d_in[4];
    const float* W1 = (const float*)d_in[5];
    const float* b1 = (const float*)d_in[6];
    const float* g1 = (const float*)d_in[7];
    const float* be1 = (const float*)d_in[8];
    const float* W2 = (const float*)d_in[9];
    const float* b2 = (const float*)d_in[10];
    const float* g2 = (const float*)d_in[11];
    const float* be2 = (const float*)d_in[12];
    const float* A  = (const float*)d_in[13];
    float* out = (float*)d_out;

    static bool init = false;
    if (!init) {
        init = true;
        cudaFuncSetAttribute(mega4_kernel, cudaFuncAttributeMaxDynamicSharedMemorySize, 200448);
    }

    reset_kernel<<<1, 32>>>();
    mega4_kernel<<<148, 768, 200448>>>(pts, W0, b0, g0, be0,
                                       W1, b1, g1, be1,
                                       W2, b2, g2, be2, A, out);
}

// round 17
// speedup vs baseline: 1.6823x; 1.0028x over previous
#include <cuda_runtime.h>

#define BIGF 1e10f

// ---------------- scratch (no allocations allowed) ----------------
__device__ int    g_cidx[8 * 1024];
__device__ float  g_pfeat[8 * 4096 * 128];
__device__ float4 g_xyzw[8 * 4096];
__device__ volatile int g_prog[8];       // fps centroids published per batch
__device__ volatile int g_pm_done;       // pmlp chunks completed
__device__ int    g_pm_next;             // pmlp work-queue counter
__device__ int    g_tile_next;           // gatt tile work-queue counter

// ---------------- f32x2 helpers ----------------
__device__ __forceinline__ void ffma2(unsigned long long& acc,
                                      unsigned long long a, unsigned long long b)
{
    asm("fma.rn.f32x2 %0, %1, %2, %0;" : "+l"(acc) : "l"(a), "l"(b));
}
__device__ __forceinline__ unsigned long long mul2(unsigned long long a,
                                                   unsigned long long b)
{
    unsigned long long r;
    asm("mul.rn.f32x2 %0, %1, %2;" : "=l"(r) : "l"(a), "l"(b));
    return r;
}
__device__ __forceinline__ unsigned long long add2(unsigned long long a,
                                                   unsigned long long b)
{
    unsigned long long r;
    asm("add.rn.f32x2 %0, %1, %2;" : "=l"(r) : "l"(a), "l"(b));
    return r;
}
__device__ __forceinline__ unsigned long long pack2(float lo, float hi)
{
    unsigned long long r;
    asm("mov.b64 %0, {%1, %2};" : "=l"(r) : "f"(lo), "f"(hi));
    return r;
}
__device__ __forceinline__ float2 unpack2(unsigned long long v)
{
    float2 r;
    asm("mov.b64 {%0, %1}, %2;" : "=f"(r.x), "=f"(r.y) : "l"(v));
    return r;
}

// =================================================================
// reset (graph replays reuse device globals)
// =================================================================
__global__ void reset_kernel()
{
    if (threadIdx.x < 8) g_prog[threadIdx.x] = 0;
    if (threadIdx.x == 8) { g_pm_done = 0; g_pm_next = 0; g_tile_next = 0; }
}

// =================================================================
// 32-row MLP layer (128-thread group) — proven bit-identical.
// =================================================================
template <int Cin, int DCP>
__device__ __forceinline__ void mlp32(
    const float* __restrict__ W, const float* __restrict__ bb,
    const float* __restrict__ gg, const float* __restrict__ be,
    int d0, const float* __restrict__ xs, float* __restrict__ ys,
    int ystr, int lane)
{
    unsigned long long acc2[DCP];
#pragma unroll
    for (int j = 0; j < DCP; ++j) acc2[j] = 0ull;
    const float* xr = xs + lane * 68;
    for (int c = 0; c < Cin; c += 4) {
        float4 x4 = *reinterpret_cast<const float4*>(xr + c);
        unsigned long long xa = pack2(x4.x, x4.y), xb = pack2(x4.z, x4.w);
#pragma unroll
        for (int j = 0; j < DCP; ++j) {
            ulonglong2 w2 = *reinterpret_cast<const ulonglong2*>(
                W + (size_t)(d0 + j) * Cin + c);
            ffma2(acc2[j], xa, w2.x);
            ffma2(acc2[j], xb, w2.y);
        }
    }
#pragma unroll
    for (int j = 0; j < DCP; ++j) {
        int d = d0 + j;
        float s = gg[d] / sqrtf(1.0f + 1e-5f);
        float2 va = unpack2(acc2[j]);
        float v = ((va.x + va.y) + bb[d]) * s + be[d];
        ys[lane * ystr + d] = fmaxf(v, 0.0f);
    }
}

// =================================================================
// MEGA v5: grid = 148 (8 fps + 140 persistent consumers), 768 thr,
// 200448B smem. fps: 16 compute warps + 1 publisher warp, named
// barrier (544 thr); publisher owns g_cidx/g_prog (release stores).
// Consumers verbatim R16 (pmlp queue -> tile queue: ballq + gatt).
// =================================================================
__global__ __launch_bounds__(768, 1) void mega5_kernel(
    const float* __restrict__ pts,
    const float* __restrict__ W0, const float* __restrict__ b0,
    const float* __restrict__ g0, const float* __restrict__ be0,
    const float* __restrict__ W1, const float* __restrict__ b1,
    const float* __restrict__ g1, const float* __restrict__ be1,
    const float* __restrict__ W2, const float* __restrict__ b2,
    const float* __restrict__ g2, const float* __restrict__ be2,
    const float* __restrict__ A, float* __restrict__ out)
{
    extern __shared__ float dynsm[];
    const int t = threadIdx.x, lane = t & 31, wp = t >> 5;

    if (blockIdx.x < 8) {
        // ======================= FPS =======================
        float4* s_xyz = reinterpret_cast<float4*>(dynsm);
        __shared__ unsigned s_wv[2][16];
        __shared__ int      s_wi[2][16];
        const int b = blockIdx.x;

        for (int j = t; j < 4096; j += 768) {
            const float* q = pts + ((size_t)b * 4096 + j) * 67;
            float x = q[0], y = q[1], z = q[2];
            float w = __fadd_rn(__fadd_rn(__fmul_rn(x, x), __fmul_rn(y, y)),
                                __fmul_rn(z, z));
            float4 v = make_float4(x, y, z, w);
            s_xyz[j] = v;
            g_xyzw[b * 4096 + j] = v;
        }
        __syncthreads();

        if (wp >= 17) return;                 // warps 17..23 leave

        if (wp == 16) {
            // ---------- publisher warp ----------
            int* prog_ptr = (int*)&g_prog[b];
            if (lane == 0) g_cidx[b * 1024] = 0;
            for (int step = 0; step < 1024; ++step) {
                asm volatile("bar.sync 1, 544;" ::: "memory");
                const int par = step & 1;
                unsigned v2 = (lane < 16) ? s_wv[par][lane] : 0u;
                int      i2 = (lane < 16) ? s_wi[par][lane] : 0x7fffffff;
                unsigned m2 = __reduce_max_sync(0xffffffffu, v2);
                int     c2  = (v2 == m2 && lane < 16) ? i2 : 0x7fffffff;
                int f       = (int)__reduce_min_sync(0xffffffffu, (unsigned)c2);
                if (lane == 0) {
                    if (step + 1 < 1024) g_cidx[b * 1024 + step + 1] = f;
                    int pv = step + 2;
                    if (pv > 1024) pv = 1024;
                    asm volatile("st.release.gpu.s32 [%0], %1;"
                                 :: "l"(prog_ptr), "r"(pv) : "memory");
                }
            }
            return;
        }

        // ---------- compute warps (t < 512) ----------
        unsigned long long px2[4], py2[4], pz2[4];
        float ds[8];
#pragma unroll
        for (int k = 0; k < 4; ++k) {
            float4 qa = s_xyz[t + (2 * k) * 512];
            float4 qb = s_xyz[t + (2 * k + 1) * 512];
            px2[k] = pack2(qa.x, qb.x);
            py2[k] = pack2(qa.y, qb.y);
            pz2[k] = pack2(qa.z, qb.z);
            ds[2 * k] = BIGF; ds[2 * k + 1] = BIGF;
        }
        float cx = s_xyz[0].x, cy = s_xyz[0].y, cz = s_xyz[0].z;

        for (int step = 0; step < 1024; ++step) {
            const unsigned long long ncx = pack2(-cx, -cx);
            const unsigned long long ncy = pack2(-cy, -cy);
            const unsigned long long ncz = pack2(-cz, -cz);
            float bv = -1.0f; int bi = 0x7fffffff;
#pragma unroll
            for (int k = 0; k < 4; ++k) {
                unsigned long long dx = add2(px2[k], ncx);
                unsigned long long dy = add2(py2[k], ncy);
                unsigned long long dz = add2(pz2[k], ncz);
                unsigned long long xx = mul2(dx, dx);
                unsigned long long yy = mul2(dy, dy);
                unsigned long long zz = mul2(dz, dz);
                unsigned long long dd = add2(add2(xx, yy), zz);
                float2 d2 = unpack2(dd);
                float n0 = fminf(ds[2 * k], d2.x);     ds[2 * k] = n0;
                float n1 = fminf(ds[2 * k + 1], d2.y); ds[2 * k + 1] = n1;
                if (n0 > bv) { bv = n0; bi = t + (2 * k) * 512; }  // ascending j
                if (n1 > bv) { bv = n1; bi = t + (2 * k + 1) * 512; }
            }
            unsigned uv = __float_as_uint(bv);
            unsigned m  = __reduce_max_sync(0xffffffffu, uv);
            int cand    = (uv == m) ? bi : 0x7fffffff;
            int mi      = (int)__reduce_min_sync(0xffffffffu, (unsigned)cand);
            const int par = step & 1;
            if (lane == 0) { s_wv[par][wp] = m; s_wi[par][wp] = mi; }
            asm volatile("bar.sync 1, 544;" ::: "memory");
            unsigned v2 = (lane < 16) ? s_wv[par][lane] : 0u;
            int      i2 = (lane < 16) ? s_wi[par][lane] : 0x7fffffff;
            unsigned m2 = __reduce_max_sync(0xffffffffu, v2);
            int     c2  = (v2 == m2 && lane < 16) ? i2 : 0x7fffffff;
            int f       = (int)__reduce_min_sync(0xffffffffu, (unsigned)c2);
            float4 c4 = s_xyz[f];
            cx = c4.x; cy = c4.y; cz = c4.z;
        }
        return;
    }

    // ======================= persistent consumer (verbatim R16) =======================
    __shared__ int    s_chunk;
    __shared__ int    s_tile;
    __shared__ float  gx[6][96];
    __shared__ float  cp[6][131];
    __shared__ int    gi[6][32];
    __shared__ int    cnt[6];
    __shared__ float4 cc[6];

    // ---- phase 1: drain pmlp work-queue (171 chunks x 192 rows) ----
    {
        const int grp = t / 128, gt = t % 128, glane = gt & 31, gwp = gt >> 5;
        float* x0g  = dynsm + grp * 6304;     // 32*68
        float* bufg = x0g + 2176;             // x1(68) / fb(129)
        for (;;) {
            if (t == 0) s_chunk = atomicAdd(&g_pm_next, 1);
            __syncthreads();
            const int c = s_chunk;
            if (c >= 171) break;
            int r0 = c * 192 + grp * 32;
            if (r0 > 32768 - 32) r0 = 32768 - 32;    // duplicate rows, same values
            for (int e = gt; e < 2048; e += 128) {
                int n = e >> 6, cch = e & 63;
                x0g[n * 68 + cch] = pts[(size_t)(r0 + n) * 67 + 3 + cch];
            }
            __syncthreads();
            mlp32<64, 16>(W0, b0, g0, be0, gwp * 16, x0g, bufg, 68, glane);
            __syncthreads();
            mlp32<64, 16>(W1, b1, g1, be1, gwp * 16, bufg, x0g, 68, glane);
            __syncthreads();
            mlp32<64, 16>(W2, b2, g2, be2, gwp * 32,      x0g, bufg, 129, glane);
            mlp32<64, 16>(W2, b2, g2, be2, gwp * 32 + 16, x0g, bufg, 129, glane);
            __syncthreads();
            for (int e = gt; e < 4096; e += 128) {
                int n = e >> 7, cch = e & 127;
                g_pfeat[(size_t)(r0 + n) * 128 + cch] = bufg[n * 129 + cch];
            }
            __syncthreads();
            if (t == 0) { __threadfence(); atomicAdd((int*)&g_pm_done, 1); }
            __syncthreads();
        }
    }

    // ---- phase 2: wait for pmlp completion (once) ----
    if (t == 0) {
        while (g_pm_done < 171) __nanosleep(256);
        __threadfence();
    }
    __syncthreads();

    // ---- phase 3: persistent tile loop ----
    for (;;) {
        if (t == 0) s_tile = atomicAdd(&g_tile_next, 1);
        __syncthreads();
        const int idx = s_tile;
        if (idx >= 1368) return;
        const int b    = idx & 7;          // idx % 8
        const int base = (idx >> 3) * 6;   // ascending base == publish order

        int lim = base + 6; if (lim > 1024) lim = 1024;
        if (t == 0) {
            while (g_prog[b] < lim) __nanosleep(128);
            __threadfence();
        }
        __syncthreads();

        // ---- local ball query for 6 centroids ----
        {
            float* cd0 = dynsm;                                   // 6*1088 floats
            int*   ci0 = reinterpret_cast<int*>(dynsm + 6 * 1088);
            if (t < 6) {
                cnt[t] = 0;
                int p = base + t; if (p > 1023) p = 1023;
                cc[t] = g_xyzw[b * 4096 + g_cidx[b * 1024 + p]];
            }
            __syncthreads();
            const float4* P4 = g_xyzw + (size_t)b * 4096;
            for (int jj = t; jj < 4096; jj += 768) {
                float4 q = P4[jj];
#pragma unroll
                for (int g = 0; g < 6; ++g) {
                    float4 cg = cc[g];
                    float e = __fadd_rn(__fadd_rn(__fmul_rn(cg.x, q.x), __fmul_rn(cg.y, q.y)),
                                        __fmul_rn(cg.z, q.z));
                    float d = __fadd_rn(__fadd_rn(__fmul_rn(-2.0f, e), cg.w), q.w);
                    if (d <= 0.04f) {
                        int pos = atomicAdd(&cnt[g], 1);
                        cd0[g * 1088 + pos] = d;
                        ci0[g * 1088 + pos] = jj;
                    }
                }
            }
            __syncthreads();

            if (wp < 6) {      // warp w extracts list w (verbatim proven logic)
                const int w = wp;
                const int n = cnt[w];
                float* wd = cd0 + w * 1088;
                int*   wi = ci0 + w * 1088;
                int first = 0;
                for (int k = 0; k < 32; ++k) {
                    int outv;
                    if (k < n) {
                        float bv = 1e30f; int bi = 0x7fffffff; int bp = 0;
                        for (int pos = lane; pos < n; pos += 32) {
                            float v = wd[pos];
                            int  idxv = wi[pos];
                            if (v < bv || (v == bv && idxv < bi)) { bv = v; bi = idxv; bp = pos; }
                        }
#pragma unroll
                        for (int o = 16; o; o >>= 1) {
                            float ov = __shfl_down_sync(0xffffffffu, bv, o);
                            int   oi = __shfl_down_sync(0xffffffffu, bi, o);
                            int   op = __shfl_down_sync(0xffffffffu, bp, o);
                            if (ov < bv || (ov == bv && oi < bi)) { bv = ov; bi = oi; bp = op; }
                        }
                        bi = __shfl_sync(0xffffffffu, bi, 0);
                        bp = __shfl_sync(0xffffffffu, bp, 0);
                        if (lane == 0) wd[bp] = 1e30f;
                        __syncwarp();
                        if (k == 0) first = bi;
                        outv = bi;
                    } else {
                        outv = first;
                    }
                    if (lane == 0) gi[w][k] = outv;
                }
            }
        }

        // ---- gatt (verbatim R14 v5) ----
        {
            float* As  = dynsm;                 // 16768 floats (overlaid by att)
            float* att = dynsm;                 // 6 * 4128
            float* fb  = dynsm + 6 * 4128;      // 6 * 4224
            const int gp = wp % 3;
            const int s  = wp / 3;
            const int d0 = s * 16;
            const int gA = 2 * gp, gB = 2 * gp + 1;

            __syncthreads();   // ballq lists dead before As overlay
            for (int e = t; e < 4192; e += 768)
                reinterpret_cast<float4*>(As)[e] = reinterpret_cast<const float4*>(A)[e];

            for (int e = t; e < 786; e += 768) {
                int gg = e / 131, c = e - gg * 131;
                int p = base + gg; if (p > 1023) p = 1023;
                int cid = g_cidx[b * 1024 + p];
                cp[gg][c] = (c < 3) ? pts[((size_t)b * 4096 + cid) * 67 + c]
                                    : g_pfeat[((size_t)b * 4096 + cid) * 128 + (c - 3)];
            }
            __syncthreads();
            if (t < 576) {
                int gg = t / 96, r = (t % 96) / 3, c = t % 3;
                gx[gg][r * 3 + c] = pts[((size_t)b * 4096 + gi[gg][r]) * 67 + c];
            }
            for (int e = t; e < 6144; e += 768) {
                int gg = e >> 10, n = (e >> 5) & 31, c4 = e & 31;
                float4 v = *reinterpret_cast<const float4*>(
                    g_pfeat + ((size_t)b * 4096 + gi[gg][n]) * 128 + c4 * 4);
                *reinterpret_cast<float4*>(fb + gg * 4224 + n * 132 + c4 * 4) = v;
            }
            __syncthreads();

            if (t < 18) {
                int gg = t / 3, c = t % 3;
                if (base + gg < 1024)
                    out[(size_t)(b * 1024 + base + gg) * 131 + c] = cp[gg][c];
            }

            unsigned long long accA[8], accB[8];
#pragma unroll
            for (int jj = 0; jj < 8; ++jj) { accA[jj] = 0ull; accB[jj] = 0ull; }
            const float* fbA = fb + gA * 4224 + lane * 132;
            const float* fbB = fb + gB * 4224 + lane * 132;
            const float* gxA = gx[gA] + lane * 3;
            const float* gxB = gx[gB] + lane * 3;
            const float* cpA = cp[gA];
            const float* cpB = cp[gB];

#pragma unroll
            for (int c = 0; c < 3; ++c) {
                float dvA = gxA[c] - cpA[c];
                float dvB = gxB[c] - cpB[c];
                unsigned long long pA = pack2(dvA, dvA);
                unsigned long long pB = pack2(dvB, dvB);
                const ulonglong2* Ar = reinterpret_cast<const ulonglong2*>(As + c * 128 + d0);
#pragma unroll
                for (int j2 = 0; j2 < 4; ++j2) {
                    ulonglong2 w = Ar[j2];
                    ffma2(accA[2 * j2], pA, w.x); ffma2(accA[2 * j2 + 1], pA, w.y);
                    ffma2(accB[2 * j2], pB, w.x); ffma2(accB[2 * j2 + 1], pB, w.y);
                }
            }
#pragma unroll 4
            for (int cc2 = 0; cc2 < 128; cc2 += 4) {
                float4 a4 = *reinterpret_cast<const float4*>(fbA + cc2);
                float4 b4 = *reinterpret_cast<const float4*>(fbB + cc2);
                float fa[4] = { a4.x, a4.y, a4.z, a4.w };
                float fbv[4] = { b4.x, b4.y, b4.z, b4.w };
#pragma unroll
                for (int u = 0; u < 4; ++u) {
                    float dvA = fa[u] - cpA[cc2 + u + 3];
                    float dvB = fbv[u] - cpB[cc2 + u + 3];
                    unsigned long long pA = pack2(dvA, dvA);
                    unsigned long long pB = pack2(dvB, dvB);
                    const ulonglong2* Ar = reinterpret_cast<const ulonglong2*>(As + (cc2 + u + 3) * 128 + d0);
#pragma unroll
                    for (int j2 = 0; j2 < 4; ++j2) {
                        ulonglong2 w = Ar[j2];
                        ffma2(accA[2 * j2], pA, w.x); ffma2(accA[2 * j2 + 1], pA, w.y);
                        ffma2(accB[2 * j2], pB, w.x); ffma2(accB[2 * j2 + 1], pB, w.y);
                    }
                }
            }
            __syncthreads();   // done reading As before overlay

            float* agA = att + gA * 4128 + lane * 129 + d0;
            float* agB = att + gB * 4128 + lane * 129 + d0;
#pragma unroll
            for (int jj = 0; jj < 8; ++jj) {
                float2 vA = unpack2(accA[jj]);
                float2 vB = unpack2(accB[jj]);
                agA[2 * jj]     = (vA.x >= 0.f) ? vA.x : 0.2f * vA.x;
                agA[2 * jj + 1] = (vA.y >= 0.f) ? vA.y : 0.2f * vA.y;
                agB[2 * jj]     = (vB.x >= 0.f) ? vB.x : 0.2f * vB.x;
                agB[2 * jj + 1] = (vB.y >= 0.f) ? vB.y : 0.2f * vB.y;
            }
            __syncthreads();

            {
                int gg = t >> 7, d = t & 127;
                const float* av = att + gg * 4128;
                const float* fv = fb + gg * 4224;
                float m = -3.4e38f;
#pragma unroll
                for (int n = 0; n < 32; ++n) m = fmaxf(m, av[n * 129 + d]);
                float ssum = 0.f, gacc = 0.f;
#pragma unroll
                for (int n = 0; n < 32; ++n) {
                    float ev = expf(av[n * 129 + d] - m);
                    ssum += ev;
                    gacc += ev * fv[n * 132 + d];
                }
                if (base + gg < 1024)
                    out[(size_t)(b * 1024 + base + gg) * 131 + 3 + d] = gacc / ssum;
            }
            __syncthreads();   // smem dead before next tile
        }
    }
}

// =================================================================
extern "C" void kernel_launch(void* const* d_in, const int* in_sizes, int n_in,
                              void* d_out, int out_size)
{
    const float* pts = (const float*)d_in[0];
    const float* W0 = (const float*)d_in[1];
    const float* b0 = (const float*)d_in[2];
    const float* g0 = (const float*)d_in[3];
    const float* be0 = (const float*)d_in[4];
    const float* W1 = (const float*)d_in[5];
    const float* b1 = (const float*)d_in[6];
    const float* g1 = (const float*)d_in[7];
    const float* be1 = (const float*)d_in[8];
    const float* W2 = (const float*)d_in[9];
    const float* b2 = (const float*)d_in[10];
    const float* g2 = (const float*)d_in[11];
    const float* be2 = (const float*)d_in[12];
    const float* A  = (const float*)d_in[13];
    float* out = (float*)d_out;

    static bool init = false;
    if (!init) {
        init = true;
        cudaFuncSetAttribute(mega5_kernel, cudaFuncAttributeMaxDynamicSharedMemorySize, 200448);
    }

    reset_kernel<<<1, 32>>>();
    mega5_kernel<<<148, 768, 200448>>>(pts, W0, b0, g0, be0,
                                       W1, b1, g1, be1,
                                       W2, b2, g2, be2, A, out);
}